// round 1
// baseline (speedup 1.0000x reference)
#include <cuda_runtime.h>
#include <math.h>

// Problem constants
#define BATCH 4
#define NQ 2048
#define NK 2048
#define DM 1024

// GEMM tiling
#define BM 128
#define BN 128
#define BK 16
#define NTHREADS 256

// Scratch (device globals: no allocation allowed in kernel_launch)
__device__ float g_Qp[BATCH * NQ * DM];       // Qp -> logpQ (in place)
__device__ float g_Kp[BATCH * NK * DM];       // Kp -> pK (in place)
__device__ float g_Vp[BATCH * NK * DM];       // Vp
__device__ float g_negent[BATCH * NK];        // sum pK*logpK per (b,j)
__device__ float g_attn[BATCH * NQ * NK];     // fallback if harness wants only `out`

// ---------------------------------------------------------------------------
// Generic fp32 tiled GEMM: C = A * op(B) (+ epilogue)
//   BT=true : B is [N,K] row-major (C[m,n] = sum_k A[m,k]*B[n,k])   (NT)
//   BT=false: B is [K,N] row-major (C[m,n] = sum_k A[m,k]*B[k,n])   (NN)
//   EPI=0: none; EPI=1: + vec[n]; EPI=2: - vec[n]
// All of M,N multiples of 128; K multiple of 16. blockIdx.z = batch.
// ---------------------------------------------------------------------------
template<bool BT, int EPI>
__global__ void __launch_bounds__(NTHREADS)
sgemm_kernel(const float* __restrict__ Ag, const float* __restrict__ Bg,
             const float* __restrict__ vecg, float* __restrict__ Cg,
             int M, int N, int K,
             long long sA, long long sB, long long sC, long long sV)
{
    const float* A = Ag + (long long)blockIdx.z * sA;
    const float* B = Bg + (long long)blockIdx.z * sB;
    float*       C = Cg + (long long)blockIdx.z * sC;
    const float* v = (EPI > 0) ? (vecg + (long long)blockIdx.z * sV) : nullptr;

    __shared__ float As[2][BK][BM];
    __shared__ float Bs[2][BK][BN];

    const int tid = threadIdx.x;
    const int m0 = blockIdx.y * BM;
    const int n0 = blockIdx.x * BN;

    // A loader: tile BM x BK = 512 float4, 2 per thread. Stored transposed As[k][m].
    const int arow0 = tid >> 2;                 // 0..63
    const int akv0  = (tid & 3) * 4;
    const int arow1 = (tid + 256) >> 2;         // 64..127
    const int akv1  = akv0;                     // ((tid+256)&3)==(tid&3)

    // B loader
    int brow0, bcv0, brow1, bcv1;
    if (BT) { // [N,K]: tile BN x BK, stored transposed Bs[k][n]
        brow0 = tid >> 2;        bcv0 = (tid & 3) * 4;
        brow1 = (tid + 256) >> 2; bcv1 = bcv0;
    } else {  // [K,N]: tile BK x BN, natural layout Bs[k][n]
        brow0 = tid >> 5;        bcv0 = (tid & 31) * 4;
        brow1 = (tid + 256) >> 5; bcv1 = bcv0;
    }

    const int tx = tid & 15, ty = tid >> 4;
    const int rm = ty * 4;   // rows rm..rm+3 and rm+64..rm+67
    const int cn = tx * 4;   // cols cn..cn+3 and cn+64..cn+67

    float acc[2][2][4][4];
    #pragma unroll
    for (int i = 0; i < 2; i++)
        #pragma unroll
        for (int j = 0; j < 2; j++)
            #pragma unroll
            for (int r = 0; r < 4; r++)
                #pragma unroll
                for (int c = 0; c < 4; c++) acc[i][j][r][c] = 0.f;

    const int nt = K / BK;
    float4 la0, la1, lb0, lb1;

    // ---- load tile 0 ----
    la0 = *(const float4*)&A[(size_t)(m0 + arow0) * K + akv0];
    la1 = *(const float4*)&A[(size_t)(m0 + arow1) * K + akv1];
    if (BT) {
        lb0 = *(const float4*)&B[(size_t)(n0 + brow0) * K + bcv0];
        lb1 = *(const float4*)&B[(size_t)(n0 + brow1) * K + bcv1];
    } else {
        lb0 = *(const float4*)&B[(size_t)brow0 * N + n0 + bcv0];
        lb1 = *(const float4*)&B[(size_t)brow1 * N + n0 + bcv1];
    }
    {
        As[0][akv0 + 0][arow0] = la0.x; As[0][akv0 + 1][arow0] = la0.y;
        As[0][akv0 + 2][arow0] = la0.z; As[0][akv0 + 3][arow0] = la0.w;
        As[0][akv1 + 0][arow1] = la1.x; As[0][akv1 + 1][arow1] = la1.y;
        As[0][akv1 + 2][arow1] = la1.z; As[0][akv1 + 3][arow1] = la1.w;
        if (BT) {
            Bs[0][bcv0 + 0][brow0] = lb0.x; Bs[0][bcv0 + 1][brow0] = lb0.y;
            Bs[0][bcv0 + 2][brow0] = lb0.z; Bs[0][bcv0 + 3][brow0] = lb0.w;
            Bs[0][bcv1 + 0][brow1] = lb1.x; Bs[0][bcv1 + 1][brow1] = lb1.y;
            Bs[0][bcv1 + 2][brow1] = lb1.z; Bs[0][bcv1 + 3][brow1] = lb1.w;
        } else {
            *(float4*)&Bs[0][brow0][bcv0] = lb0;
            *(float4*)&Bs[0][brow1][bcv1] = lb1;
        }
    }
    __syncthreads();

    for (int t = 0; t < nt; t++) {
        const int buf = t & 1;
        if (t + 1 < nt) {
            const int k0 = (t + 1) * BK;
            la0 = *(const float4*)&A[(size_t)(m0 + arow0) * K + k0 + akv0];
            la1 = *(const float4*)&A[(size_t)(m0 + arow1) * K + k0 + akv1];
            if (BT) {
                lb0 = *(const float4*)&B[(size_t)(n0 + brow0) * K + k0 + bcv0];
                lb1 = *(const float4*)&B[(size_t)(n0 + brow1) * K + k0 + bcv1];
            } else {
                lb0 = *(const float4*)&B[(size_t)(k0 + brow0) * N + n0 + bcv0];
                lb1 = *(const float4*)&B[(size_t)(k0 + brow1) * N + n0 + bcv1];
            }
        }
        #pragma unroll
        for (int k = 0; k < BK; k++) {
            float4 a0 = *(const float4*)&As[buf][k][rm];
            float4 a1 = *(const float4*)&As[buf][k][rm + 64];
            float4 b0 = *(const float4*)&Bs[buf][k][cn];
            float4 b1 = *(const float4*)&Bs[buf][k][cn + 64];
            float ar[8] = {a0.x, a0.y, a0.z, a0.w, a1.x, a1.y, a1.z, a1.w};
            float br[8] = {b0.x, b0.y, b0.z, b0.w, b1.x, b1.y, b1.z, b1.w};
            #pragma unroll
            for (int i = 0; i < 2; i++)
                #pragma unroll
                for (int r = 0; r < 4; r++)
                    #pragma unroll
                    for (int j = 0; j < 2; j++)
                        #pragma unroll
                        for (int c = 0; c < 4; c++)
                            acc[i][j][r][c] += ar[i * 4 + r] * br[j * 4 + c];
        }
        if (t + 1 < nt) {
            const int nb = buf ^ 1;
            As[nb][akv0 + 0][arow0] = la0.x; As[nb][akv0 + 1][arow0] = la0.y;
            As[nb][akv0 + 2][arow0] = la0.z; As[nb][akv0 + 3][arow0] = la0.w;
            As[nb][akv1 + 0][arow1] = la1.x; As[nb][akv1 + 1][arow1] = la1.y;
            As[nb][akv1 + 2][arow1] = la1.z; As[nb][akv1 + 3][arow1] = la1.w;
            if (BT) {
                Bs[nb][bcv0 + 0][brow0] = lb0.x; Bs[nb][bcv0 + 1][brow0] = lb0.y;
                Bs[nb][bcv0 + 2][brow0] = lb0.z; Bs[nb][bcv0 + 3][brow0] = lb0.w;
                Bs[nb][bcv1 + 0][brow1] = lb1.x; Bs[nb][bcv1 + 1][brow1] = lb1.y;
                Bs[nb][bcv1 + 2][brow1] = lb1.z; Bs[nb][bcv1 + 3][brow1] = lb1.w;
            } else {
                *(float4*)&Bs[nb][brow0][bcv0] = lb0;
                *(float4*)&Bs[nb][brow1][bcv1] = lb1;
            }
            __syncthreads();
        }
    }

    // epilogue
    #pragma unroll
    for (int i = 0; i < 2; i++)
        #pragma unroll
        for (int r = 0; r < 4; r++) {
            const int grow = m0 + i * 64 + rm + r;
            #pragma unroll
            for (int j = 0; j < 2; j++) {
                const int gcol = n0 + j * 64 + cn;
                float4 val;
                val.x = acc[i][j][r][0]; val.y = acc[i][j][r][1];
                val.z = acc[i][j][r][2]; val.w = acc[i][j][r][3];
                if (EPI == 1) {
                    float4 vv = *(const float4*)&v[gcol];
                    val.x += vv.x; val.y += vv.y; val.z += vv.z; val.w += vv.w;
                } else if (EPI == 2) {
                    float4 vv = *(const float4*)&v[gcol];
                    val.x -= vv.x; val.y -= vv.y; val.z -= vv.z; val.w -= vv.w;
                }
                *(float4*)&C[(size_t)grow * N + gcol] = val;
            }
        }
}

// ---------------------------------------------------------------------------
// Row reductions. 256 threads/row.
// ---------------------------------------------------------------------------
__device__ __forceinline__ float warp_max(float v) {
    #pragma unroll
    for (int o = 16; o; o >>= 1) v = fmaxf(v, __shfl_xor_sync(0xffffffffu, v, o));
    return v;
}
__device__ __forceinline__ float warp_sum(float v) {
    #pragma unroll
    for (int o = 16; o; o >>= 1) v += __shfl_xor_sync(0xffffffffu, v, o);
    return v;
}

// X[row] -= logsumexp(X[row]); D = 1024 fixed
__global__ void __launch_bounds__(256) logsoftmax_rows(float* __restrict__ X)
{
    const int D = DM;
    float* row = X + (size_t)blockIdx.x * D;
    const int t = threadIdx.x;
    __shared__ float sred[8];

    float x[4];
    #pragma unroll
    for (int i = 0; i < 4; i++) x[i] = row[t + 256 * i];

    float m = fmaxf(fmaxf(x[0], x[1]), fmaxf(x[2], x[3]));
    m = warp_max(m);
    if ((t & 31) == 0) sred[t >> 5] = m;
    __syncthreads();
    if (t < 32) {
        float v = (t < 8) ? sred[t] : -INFINITY;
        #pragma unroll
        for (int o = 4; o; o >>= 1) v = fmaxf(v, __shfl_xor_sync(0xffffffffu, v, o));
        if (t == 0) sred[0] = v;
    }
    __syncthreads();
    m = sred[0];
    __syncthreads();

    float s = 0.f;
    #pragma unroll
    for (int i = 0; i < 4; i++) s += expf(x[i] - m);
    s = warp_sum(s);
    if ((t & 31) == 0) sred[t >> 5] = s;
    __syncthreads();
    if (t < 32) {
        float v = (t < 8) ? sred[t] : 0.f;
        #pragma unroll
        for (int o = 4; o; o >>= 1) v += __shfl_xor_sync(0xffffffffu, v, o);
        if (t == 0) sred[0] = v;
    }
    __syncthreads();
    const float lse = m + logf(sred[0]);

    #pragma unroll
    for (int i = 0; i < 4; i++) row[t + 256 * i] = x[i] - lse;
}

// X[row] -> softmax(X[row]) in place; negent[row] = sum p*logp. D = 1024 fixed
__global__ void __launch_bounds__(256) softmax_ent_rows(float* __restrict__ X,
                                                        float* __restrict__ negent)
{
    const int D = DM;
    float* row = X + (size_t)blockIdx.x * D;
    const int t = threadIdx.x;
    __shared__ float sred[8];

    float x[4];
    #pragma unroll
    for (int i = 0; i < 4; i++) x[i] = row[t + 256 * i];

    float m = fmaxf(fmaxf(x[0], x[1]), fmaxf(x[2], x[3]));
    m = warp_max(m);
    if ((t & 31) == 0) sred[t >> 5] = m;
    __syncthreads();
    if (t < 32) {
        float v = (t < 8) ? sred[t] : -INFINITY;
        #pragma unroll
        for (int o = 4; o; o >>= 1) v = fmaxf(v, __shfl_xor_sync(0xffffffffu, v, o));
        if (t == 0) sred[0] = v;
    }
    __syncthreads();
    m = sred[0];
    __syncthreads();

    float s = 0.f;
    #pragma unroll
    for (int i = 0; i < 4; i++) s += expf(x[i] - m);
    s = warp_sum(s);
    if ((t & 31) == 0) sred[t >> 5] = s;
    __syncthreads();
    if (t < 32) {
        float v = (t < 8) ? sred[t] : 0.f;
        #pragma unroll
        for (int o = 4; o; o >>= 1) v += __shfl_xor_sync(0xffffffffu, v, o);
        if (t == 0) sred[0] = v;
    }
    __syncthreads();
    const float lse = m + logf(sred[0]);

    float se = 0.f;
    #pragma unroll
    for (int i = 0; i < 4; i++) {
        const float lp = x[i] - lse;
        const float p = expf(lp);
        row[t + 256 * i] = p;
        se += p * lp;
    }
    se = warp_sum(se);
    if ((t & 31) == 0) sred[t >> 5] = se;
    __syncthreads();
    if (t < 32) {
        float v = (t < 8) ? sred[t] : 0.f;
        #pragma unroll
        for (int o = 4; o; o >>= 1) v += __shfl_xor_sync(0xffffffffu, v, o);
        if (t == 0) negent[blockIdx.x] = v;
    }
}

// attn row softmax in place; D = 2048 fixed (8 elems/thread)
__global__ void __launch_bounds__(256) attn_softmax_rows(float* __restrict__ X)
{
    const int D = NK;
    float* row = X + (size_t)blockIdx.x * D;
    const int t = threadIdx.x;
    __shared__ float sred[8];

    float x[8];
    #pragma unroll
    for (int i = 0; i < 8; i++) x[i] = row[t + 256 * i];

    float m = -INFINITY;
    #pragma unroll
    for (int i = 0; i < 8; i++) m = fmaxf(m, x[i]);
    m = warp_max(m);
    if ((t & 31) == 0) sred[t >> 5] = m;
    __syncthreads();
    if (t < 32) {
        float v = (t < 8) ? sred[t] : -INFINITY;
        #pragma unroll
        for (int o = 4; o; o >>= 1) v = fmaxf(v, __shfl_xor_sync(0xffffffffu, v, o));
        if (t == 0) sred[0] = v;
    }
    __syncthreads();
    m = sred[0];
    __syncthreads();

    float ex[8];
    float s = 0.f;
    #pragma unroll
    for (int i = 0; i < 8; i++) { ex[i] = expf(x[i] - m); s += ex[i]; }
    s = warp_sum(s);
    if ((t & 31) == 0) sred[t >> 5] = s;
    __syncthreads();
    if (t < 32) {
        float v = (t < 8) ? sred[t] : 0.f;
        #pragma unroll
        for (int o = 4; o; o >>= 1) v += __shfl_xor_sync(0xffffffffu, v, o);
        if (t == 0) sred[0] = v;
    }
    __syncthreads();
    const float inv = 1.f / sred[0];

    #pragma unroll
    for (int i = 0; i < 8; i++) row[t + 256 * i] = ex[i] * inv;
}

// ---------------------------------------------------------------------------
// Launch
// ---------------------------------------------------------------------------
extern "C" void kernel_launch(void* const* d_in, const int* in_sizes, int n_in,
                              void* d_out, int out_size)
{
    const float* Q  = (const float*)d_in[0];
    const float* K  = (const float*)d_in[1];
    const float* V  = (const float*)d_in[2];
    const float* Wq = (const float*)d_in[3];
    const float* bq = (const float*)d_in[4];
    const float* Wk = (const float*)d_in[5];
    const float* bk = (const float*)d_in[6];
    const float* Wv = (const float*)d_in[7];
    const float* bv = (const float*)d_in[8];

    float* out = (float*)d_out;

    const long long outElems  = (long long)BATCH * NQ * DM;   // 8,388,608
    const long long attnElems = (long long)BATCH * NQ * NK;   // 16,777,216

    // attn destination: into d_out after `out` if the harness expects both outputs,
    // else into scratch.
    float* attn;
    {
        float* attn_dev = nullptr;
        cudaGetSymbolAddress((void**)&attn_dev, g_attn);
        attn = ((long long)out_size >= outElems + attnElems) ? (out + outElems) : attn_dev;
    }

    float *Qp, *Kp, *Vp, *negent;
    cudaGetSymbolAddress((void**)&Qp, g_Qp);
    cudaGetSymbolAddress((void**)&Kp, g_Kp);
    cudaGetSymbolAddress((void**)&Vp, g_Vp);
    cudaGetSymbolAddress((void**)&negent, g_negent);

    const int Mrows = BATCH * NQ;  // 8192

    // 1) Projections: P = X @ W^T + b   (NT, bias epilogue)
    {
        dim3 grid(DM / BN, Mrows / BM, 1);
        sgemm_kernel<true, 1><<<grid, NTHREADS>>>(Q, Wq, bq, Qp, Mrows, DM, DM, 0, 0, 0, 0);
        sgemm_kernel<true, 1><<<grid, NTHREADS>>>(K, Wk, bk, Kp, Mrows, DM, DM, 0, 0, 0, 0);
        sgemm_kernel<true, 1><<<grid, NTHREADS>>>(V, Wv, bv, Vp, Mrows, DM, DM, 0, 0, 0, 0);
    }

    // 2) logpQ = log_softmax(Qp); pK = softmax(Kp), negent = sum pK*logpK
    logsoftmax_rows<<<Mrows, 256>>>(Qp);
    softmax_ent_rows<<<Mrows, 256>>>(Kp, negent);

    // 3) scores[b,i,j] = sum_d logpQ[b,i,d]*pK[b,j,d] - negent[b,j]   (NT, minus-vec epilogue)
    {
        dim3 grid(NK / BN, NQ / BM, BATCH);
        sgemm_kernel<true, 2><<<grid, NTHREADS>>>(
            Qp, Kp, negent, attn, NQ, NK, DM,
            (long long)NQ * DM, (long long)NK * DM, (long long)NQ * NK, (long long)NK);
    }

    // 4) attn = softmax(scores) over j, in place
    attn_softmax_rows<<<BATCH * NQ, 256>>>(attn);

    // 5) out[b,i,d] = sum_j attn[b,i,j] * Vp[b,j,d]   (NN)
    {
        dim3 grid(DM / BN, NQ / BM, BATCH);
        sgemm_kernel<false, 0><<<grid, NTHREADS>>>(
            attn, Vp, nullptr, out, NQ, DM, NK,
            (long long)NQ * NK, (long long)NK * DM, (long long)NQ * DM, 0);
    }
}

// round 3
// speedup vs baseline: 2.1940x; 2.1940x over previous
#include <cuda_runtime.h>
#include <cuda_bf16.h>
#include <stdint.h>
#include <math.h>

// Problem constants
#define BATCH 4
#define NQ 2048
#define NK 2048
#define DM 1024

// ---------------------------------------------------------------------------
// Scratch (device globals: no allocation allowed)
// ---------------------------------------------------------------------------
__device__ float g_Qp[BATCH * NQ * DM];
__device__ float g_Kp[BATCH * NK * DM];
__device__ float g_Vp[BATCH * NK * DM];
__device__ float g_negent[BATCH * NK];
__device__ float g_attn[BATCH * NQ * NK];

__device__ __nv_bfloat16 g_Qh[BATCH * NQ * DM],  g_Ql[BATCH * NQ * DM];
__device__ __nv_bfloat16 g_Kh[BATCH * NK * DM],  g_Kl[BATCH * NK * DM];
__device__ __nv_bfloat16 g_Vh[BATCH * NK * DM],  g_Vl[BATCH * NK * DM];
__device__ __nv_bfloat16 g_Wqh[DM * DM], g_Wql[DM * DM];
__device__ __nv_bfloat16 g_Wkh[DM * DM], g_Wkl[DM * DM];
__device__ __nv_bfloat16 g_Wvh[DM * DM], g_Wvl[DM * DM];
__device__ __nv_bfloat16 g_lQh[BATCH * NQ * DM], g_lQl[BATCH * NQ * DM];
__device__ __nv_bfloat16 g_pKh[BATCH * NK * DM], g_pKl[BATCH * NK * DM];
__device__ __nv_bfloat16 g_VpTh[BATCH * DM * NK], g_VpTl[BATCH * DM * NK];
__device__ __nv_bfloat16 g_Ath[BATCH * NQ * NK], g_Atl[BATCH * NQ * NK];

// ---------------------------------------------------------------------------
// Warp-MMA split-bf16 GEMM: C[M,N] = A[M,K] @ B[N,K]^T  (NT), fp32 accumulate.
// A,B given as (hi, lo) bf16 pairs; computes Ah*Bh + Ah*Bl + Al*Bh.
// EPI: 0 none, 1 += vec[n], 2 -= vec[n].
// CTA tile 128x128, 8 warps of 64x32. K-chunk = 32, cp.async double buffer.
// smem rows padded to 40 bf16 (80B) -> conflict-free ldmatrix phases.
// ---------------------------------------------------------------------------
#define KC 32
#define SROW 40

__device__ __forceinline__ void ldsm_x4(uint32_t* r, uint32_t addr) {
    asm volatile("ldmatrix.sync.aligned.m8n8.x4.shared.b16 {%0,%1,%2,%3}, [%4];"
                 : "=r"(r[0]), "=r"(r[1]), "=r"(r[2]), "=r"(r[3]) : "r"(addr));
}
__device__ __forceinline__ void mma_bf16(float* c, const uint32_t* a, uint32_t b0, uint32_t b1) {
    asm volatile(
        "mma.sync.aligned.m16n8k16.row.col.f32.bf16.bf16.f32 "
        "{%0,%1,%2,%3}, {%4,%5,%6,%7}, {%8,%9}, {%0,%1,%2,%3};"
        : "+f"(c[0]), "+f"(c[1]), "+f"(c[2]), "+f"(c[3])
        : "r"(a[0]), "r"(a[1]), "r"(a[2]), "r"(a[3]), "r"(b0), "r"(b1));
}

template<int EPI>
__global__ void __launch_bounds__(256)
wm_gemm(const __nv_bfloat16* __restrict__ Ah_, const __nv_bfloat16* __restrict__ Al_,
        const __nv_bfloat16* __restrict__ Bh_, const __nv_bfloat16* __restrict__ Bl_,
        const float* __restrict__ vec_, float* __restrict__ C_,
        int M, int N, int K,
        long long sA, long long sB, long long sC, long long sV)
{
    __shared__ __align__(16) __nv_bfloat16 As[2][128 * SROW];
    __shared__ __align__(16) __nv_bfloat16 Bs[2][128 * SROW];

    const int tid = threadIdx.x, lane = tid & 31, wid = tid >> 5;
    const int m0 = blockIdx.y * 128, n0 = blockIdx.x * 128;
    const long long bz = blockIdx.z;
    const __nv_bfloat16* Ah = Ah_ + bz * sA;
    const __nv_bfloat16* Al = Al_ + bz * sA;
    const __nv_bfloat16* Bh = Bh_ + bz * sB;
    const __nv_bfloat16* Bl = Bl_ + bz * sB;
    float* C = C_ + bz * sC;
    const float* vec = (EPI != 0) ? (vec_ + bz * sV) : nullptr;

    const int m_warp = (wid >> 2) * 64;
    const int n_warp = (wid & 3) * 32;

    const int nt = 3 * (K / KC);

    // loader: 256 threads x 2 segments x 16B covers one 128x32 bf16 tile per matrix
    const int lrow = tid >> 2;          // 0..63 (+64 on second segment)
    const int lc   = (tid & 3) * 8;     // element col within chunk (0,8,16,24)

    auto issue = [&](int t, int stage) {
        const int s  = t % 3;
        const int k0 = (t / 3) * KC;
        const __nv_bfloat16* Asrc = (s == 2) ? Al : Ah;
        const __nv_bfloat16* Bsrc = (s == 1) ? Bl : Bh;
        #pragma unroll
        for (int i = 0; i < 2; i++) {
            const int row = lrow + i * 64;
            const void* ga = Asrc + (long long)(m0 + row) * K + k0 + lc;
            uint32_t da = (uint32_t)__cvta_generic_to_shared(&As[stage][row * SROW + lc]);
            asm volatile("cp.async.cg.shared.global [%0], [%1], 16;" :: "r"(da), "l"(ga));
            const void* gb = Bsrc + (long long)(n0 + row) * K + k0 + lc;
            uint32_t db = (uint32_t)__cvta_generic_to_shared(&Bs[stage][row * SROW + lc]);
            asm volatile("cp.async.cg.shared.global [%0], [%1], 16;" :: "r"(db), "l"(gb));
        }
        asm volatile("cp.async.commit_group;");
    };

    float acc[4][4][4];
    #pragma unroll
    for (int i = 0; i < 4; i++)
        #pragma unroll
        for (int j = 0; j < 4; j++)
            #pragma unroll
            for (int r = 0; r < 4; r++) acc[i][j][r] = 0.f;

    // ldmatrix per-thread row/col components
    const int ar  = lane & 15;
    const int ac8 = (lane >> 4) & 1;
    const int br  = (lane & 7) + ((lane & 16) ? 8 : 0);
    const int bc8 = (lane >> 3) & 1;

    issue(0, 0);
    issue(1, 1);

    for (int t = 0; t < nt; t++) {
        if (t + 2 < nt) { asm volatile("cp.async.wait_group 1;"); }
        else            { asm volatile("cp.async.wait_group 0;"); }
        __syncthreads();

        const int stage = t & 1;
        const uint32_t abase = (uint32_t)__cvta_generic_to_shared(&As[stage][0]);
        const uint32_t bbase = (uint32_t)__cvta_generic_to_shared(&Bs[stage][0]);

        #pragma unroll
        for (int k16 = 0; k16 < 2; k16++) {
            uint32_t a[4][4], b[2][4];
            #pragma unroll
            for (int tm = 0; tm < 4; tm++) {
                uint32_t addr = abase +
                    ((m_warp + tm * 16 + ar) * SROW + k16 * 16 + ac8 * 8) * 2;
                ldsm_x4(a[tm], addr);
            }
            #pragma unroll
            for (int p = 0; p < 2; p++) {
                uint32_t addr = bbase +
                    ((n_warp + p * 16 + br) * SROW + k16 * 16 + bc8 * 8) * 2;
                ldsm_x4(b[p], addr);
            }
            #pragma unroll
            for (int tm = 0; tm < 4; tm++)
                #pragma unroll
                for (int tn = 0; tn < 4; tn++)
                    mma_bf16(acc[tm][tn], a[tm],
                             b[tn >> 1][(tn & 1) * 2], b[tn >> 1][(tn & 1) * 2 + 1]);
        }
        __syncthreads();
        if (t + 2 < nt) issue(t + 2, stage);
    }

    // epilogue
    #pragma unroll
    for (int tm = 0; tm < 4; tm++) {
        #pragma unroll
        for (int tn = 0; tn < 4; tn++) {
            const int row = m0 + m_warp + tm * 16 + (lane >> 2);
            const int col = n0 + n_warp + tn * 8 + (lane & 3) * 2;
            float2 v0 = make_float2(acc[tm][tn][0], acc[tm][tn][1]);
            float2 v1 = make_float2(acc[tm][tn][2], acc[tm][tn][3]);
            if (EPI != 0) {
                const float2 vv = *(const float2*)&vec[col];
                if (EPI == 1) { v0.x += vv.x; v0.y += vv.y; v1.x += vv.x; v1.y += vv.y; }
                else          { v0.x -= vv.x; v0.y -= vv.y; v1.x -= vv.x; v1.y -= vv.y; }
            }
            *(float2*)&C[(long long)row * N + col] = v0;
            *(float2*)&C[(long long)(row + 8) * N + col] = v1;
        }
    }
}

// ---------------------------------------------------------------------------
// fp32 -> (bf16 hi, bf16 lo) split, vectorized x4
// ---------------------------------------------------------------------------
__global__ void __launch_bounds__(256) split_kernel(const float* __restrict__ x,
                                                    __nv_bfloat16* __restrict__ hi,
                                                    __nv_bfloat16* __restrict__ lo,
                                                    long long n4)
{
    const long long i = (long long)blockIdx.x * blockDim.x + threadIdx.x;
    if (i >= n4) return;
    const float4 v = ((const float4*)x)[i];
    __nv_bfloat16 h0 = __float2bfloat16(v.x);
    __nv_bfloat16 h1 = __float2bfloat16(v.y);
    __nv_bfloat16 h2 = __float2bfloat16(v.z);
    __nv_bfloat16 h3 = __float2bfloat16(v.w);
    __nv_bfloat162* H = (__nv_bfloat162*)hi;
    __nv_bfloat162* L = (__nv_bfloat162*)lo;
    H[2*i]   = __nv_bfloat162(h0, h1);
    H[2*i+1] = __nv_bfloat162(h2, h3);
    L[2*i]   = __nv_bfloat162(__float2bfloat16(v.x - __bfloat162float(h0)),
                              __float2bfloat16(v.y - __bfloat162float(h1)));
    L[2*i+1] = __nv_bfloat162(__float2bfloat16(v.z - __bfloat162float(h2)),
                              __float2bfloat16(v.w - __bfloat162float(h3)));
}

// Vp [b, 2048, 1024] fp32 -> VpT [b, 1024, 2048] split bf16
__global__ void __launch_bounds__(256) transpose_split_kernel(const float* __restrict__ src,
                                                              __nv_bfloat16* __restrict__ dhi,
                                                              __nv_bfloat16* __restrict__ dlo)
{
    __shared__ float tile[32][33];
    const long long b = blockIdx.z;
    const float* S = src + b * (long long)NK * DM;
    const int x0 = blockIdx.x * 32;   // src col (headdim)
    const int y0 = blockIdx.y * 32;   // src row (token)
    #pragma unroll
    for (int j = 0; j < 32; j += 8)
        tile[threadIdx.y + j][threadIdx.x] =
            S[(long long)(y0 + threadIdx.y + j) * DM + x0 + threadIdx.x];
    __syncthreads();
    __nv_bfloat16* Hh = dhi + b * (long long)DM * NK;
    __nv_bfloat16* Hl = dlo + b * (long long)DM * NK;
    #pragma unroll
    for (int j = 0; j < 32; j += 8) {
        const float v = tile[threadIdx.x][threadIdx.y + j];
        const int orow = x0 + threadIdx.y + j;
        const int ocol = y0 + threadIdx.x;
        const __nv_bfloat16 h = __float2bfloat16(v);
        Hh[(long long)orow * NK + ocol] = h;
        Hl[(long long)orow * NK + ocol] = __float2bfloat16(v - __bfloat162float(h));
    }
}

// ---------------------------------------------------------------------------
// Row reductions
// ---------------------------------------------------------------------------
__device__ __forceinline__ float warp_max(float v) {
    #pragma unroll
    for (int o = 16; o; o >>= 1) v = fmaxf(v, __shfl_xor_sync(0xffffffffu, v, o));
    return v;
}
__device__ __forceinline__ float warp_sum(float v) {
    #pragma unroll
    for (int o = 16; o; o >>= 1) v += __shfl_xor_sync(0xffffffffu, v, o);
    return v;
}

__global__ void __launch_bounds__(256) logsoftmax_rows(float* __restrict__ X)
{
    float* row = X + (size_t)blockIdx.x * DM;
    const int t = threadIdx.x;
    __shared__ float sred[8];
    float x[4];
    #pragma unroll
    for (int i = 0; i < 4; i++) x[i] = row[t + 256 * i];
    float m = fmaxf(fmaxf(x[0], x[1]), fmaxf(x[2], x[3]));
    m = warp_max(m);
    if ((t & 31) == 0) sred[t >> 5] = m;
    __syncthreads();
    if (t < 32) {
        float v = (t < 8) ? sred[t] : -INFINITY;
        #pragma unroll
        for (int o = 4; o; o >>= 1) v = fmaxf(v, __shfl_xor_sync(0xffffffffu, v, o));
        if (t == 0) sred[0] = v;
    }
    __syncthreads();
    m = sred[0];
    __syncthreads();
    float s = 0.f;
    #pragma unroll
    for (int i = 0; i < 4; i++) s += expf(x[i] - m);
    s = warp_sum(s);
    if ((t & 31) == 0) sred[t >> 5] = s;
    __syncthreads();
    if (t < 32) {
        float v = (t < 8) ? sred[t] : 0.f;
        #pragma unroll
        for (int o = 4; o; o >>= 1) v += __shfl_xor_sync(0xffffffffu, v, o);
        if (t == 0) sred[0] = v;
    }
    __syncthreads();
    const float lse = m + logf(sred[0]);
    #pragma unroll
    for (int i = 0; i < 4; i++) row[t + 256 * i] = x[i] - lse;
}

__global__ void __launch_bounds__(256) softmax_ent_rows(float* __restrict__ X,
                                                        float* __restrict__ negent)
{
    float* row = X + (size_t)blockIdx.x * DM;
    const int t = threadIdx.x;
    __shared__ float sred[8];
    float x[4];
    #pragma unroll
    for (int i = 0; i < 4; i++) x[i] = row[t + 256 * i];
    float m = fmaxf(fmaxf(x[0], x[1]), fmaxf(x[2], x[3]));
    m = warp_max(m);
    if ((t & 31) == 0) sred[t >> 5] = m;
    __syncthreads();
    if (t < 32) {
        float v = (t < 8) ? sred[t] : -INFINITY;
        #pragma unroll
        for (int o = 4; o; o >>= 1) v = fmaxf(v, __shfl_xor_sync(0xffffffffu, v, o));
        if (t == 0) sred[0] = v;
    }
    __syncthreads();
    m = sred[0];
    __syncthreads();
    float s = 0.f;
    #pragma unroll
    for (int i = 0; i < 4; i++) s += expf(x[i] - m);
    s = warp_sum(s);
    if ((t & 31) == 0) sred[t >> 5] = s;
    __syncthreads();
    if (t < 32) {
        float v = (t < 8) ? sred[t] : 0.f;
        #pragma unroll
        for (int o = 4; o; o >>= 1) v += __shfl_xor_sync(0xffffffffu, v, o);
        if (t == 0) sred[0] = v;
    }
    __syncthreads();
    const float lse = m + logf(sred[0]);
    float se = 0.f;
    #pragma unroll
    for (int i = 0; i < 4; i++) {
        const float lp = x[i] - lse;
        const float p = expf(lp);
        row[t + 256 * i] = p;
        se += p * lp;
    }
    se = warp_sum(se);
    if ((t & 31) == 0) sred[t >> 5] = se;
    __syncthreads();
    if (t < 32) {
        float v = (t < 8) ? sred[t] : 0.f;
        #pragma unroll
        for (int o = 4; o; o >>= 1) v += __shfl_xor_sync(0xffffffffu, v, o);
        if (t == 0) negent[blockIdx.x] = v;
    }
}

__global__ void __launch_bounds__(256) attn_softmax_rows(float* __restrict__ X)
{
    float* row = X + (size_t)blockIdx.x * NK;
    const int t = threadIdx.x;
    __shared__ float sred[8];
    float x[8];
    #pragma unroll
    for (int i = 0; i < 8; i++) x[i] = row[t + 256 * i];
    float m = -INFINITY;
    #pragma unroll
    for (int i = 0; i < 8; i++) m = fmaxf(m, x[i]);
    m = warp_max(m);
    if ((t & 31) == 0) sred[t >> 5] = m;
    __syncthreads();
    if (t < 32) {
        float v = (t < 8) ? sred[t] : -INFINITY;
        #pragma unroll
        for (int o = 4; o; o >>= 1) v = fmaxf(v, __shfl_xor_sync(0xffffffffu, v, o));
        if (t == 0) sred[0] = v;
    }
    __syncthreads();
    m = sred[0];
    __syncthreads();
    float ex[8];
    float s = 0.f;
    #pragma unroll
    for (int i = 0; i < 8; i++) { ex[i] = expf(x[i] - m); s += ex[i]; }
    s = warp_sum(s);
    if ((t & 31) == 0) sred[t >> 5] = s;
    __syncthreads();
    if (t < 32) {
        float v = (t < 8) ? sred[t] : 0.f;
        #pragma unroll
        for (int o = 4; o; o >>= 1) v += __shfl_xor_sync(0xffffffffu, v, o);
        if (t == 0) sred[0] = v;
    }
    __syncthreads();
    const float inv = 1.f / sred[0];
    #pragma unroll
    for (int i = 0; i < 8; i++) row[t + 256 * i] = ex[i] * inv;
}

// ---------------------------------------------------------------------------
// Launch
// ---------------------------------------------------------------------------
static void run_split(const float* x, __nv_bfloat16* hi, __nv_bfloat16* lo, long long n)
{
    const long long n4 = n >> 2;
    split_kernel<<<(unsigned)((n4 + 255) / 256), 256>>>(x, hi, lo, n4);
}

extern "C" void kernel_launch(void* const* d_in, const int* in_sizes, int n_in,
                              void* d_out, int out_size)
{
    const float* Q  = (const float*)d_in[0];
    const float* K  = (const float*)d_in[1];
    const float* V  = (const float*)d_in[2];
    const float* Wq = (const float*)d_in[3];
    const float* bq = (const float*)d_in[4];
    const float* Wk = (const float*)d_in[5];
    const float* bk = (const float*)d_in[6];
    const float* Wv = (const float*)d_in[7];
    const float* bv = (const float*)d_in[8];

    float* out = (float*)d_out;
    const long long outElems  = (long long)BATCH * NQ * DM;
    const long long attnElems = (long long)BATCH * NQ * NK;

    float *Qp, *Kp, *Vp, *negent, *attn_scratch;
    cudaGetSymbolAddress((void**)&Qp, g_Qp);
    cudaGetSymbolAddress((void**)&Kp, g_Kp);
    cudaGetSymbolAddress((void**)&Vp, g_Vp);
    cudaGetSymbolAddress((void**)&negent, g_negent);
    cudaGetSymbolAddress((void**)&attn_scratch, g_attn);
    float* attn = ((long long)out_size >= outElems + attnElems) ? (out + outElems) : attn_scratch;

    __nv_bfloat16 *Qh, *Ql, *Kh, *Kl, *Vh, *Vl, *Wqh, *Wql, *Wkh, *Wkl, *Wvh, *Wvl;
    __nv_bfloat16 *lQh, *lQl, *pKh, *pKl, *VpTh, *VpTl, *Ath, *Atl;
    cudaGetSymbolAddress((void**)&Qh, g_Qh);   cudaGetSymbolAddress((void**)&Ql, g_Ql);
    cudaGetSymbolAddress((void**)&Kh, g_Kh);   cudaGetSymbolAddress((void**)&Kl, g_Kl);
    cudaGetSymbolAddress((void**)&Vh, g_Vh);   cudaGetSymbolAddress((void**)&Vl, g_Vl);
    cudaGetSymbolAddress((void**)&Wqh, g_Wqh); cudaGetSymbolAddress((void**)&Wql, g_Wql);
    cudaGetSymbolAddress((void**)&Wkh, g_Wkh); cudaGetSymbolAddress((void**)&Wkl, g_Wkl);
    cudaGetSymbolAddress((void**)&Wvh, g_Wvh); cudaGetSymbolAddress((void**)&Wvl, g_Wvl);
    cudaGetSymbolAddress((void**)&lQh, g_lQh); cudaGetSymbolAddress((void**)&lQl, g_lQl);
    cudaGetSymbolAddress((void**)&pKh, g_pKh); cudaGetSymbolAddress((void**)&pKl, g_pKl);
    cudaGetSymbolAddress((void**)&VpTh, g_VpTh); cudaGetSymbolAddress((void**)&VpTl, g_VpTl);
    cudaGetSymbolAddress((void**)&Ath, g_Ath); cudaGetSymbolAddress((void**)&Atl, g_Atl);

    const int Mrows = BATCH * NQ;  // 8192

    // 1) split inputs + weights to bf16 hi/lo
    run_split(Q, Qh, Ql, (long long)Mrows * DM);
    run_split(K, Kh, Kl, (long long)Mrows * DM);
    run_split(V, Vh, Vl, (long long)Mrows * DM);
    run_split(Wq, Wqh, Wql, (long long)DM * DM);
    run_split(Wk, Wkh, Wkl, (long long)DM * DM);
    run_split(Wv, Wvh, Wvl, (long long)DM * DM);

    // 2) projections: P = X @ W^T + b  (batch-fused, weight shared)
    {
        dim3 grid(DM / 128, Mrows / 128, 1);
        wm_gemm<1><<<grid, 256>>>(Qh, Ql, Wqh, Wql, bq, Qp, Mrows, DM, DM, 0, 0, 0, 0);
        wm_gemm<1><<<grid, 256>>>(Kh, Kl, Wkh, Wkl, bk, Kp, Mrows, DM, DM, 0, 0, 0, 0);
        wm_gemm<1><<<grid, 256>>>(Vh, Vl, Wvh, Wvl, bv, Vp, Mrows, DM, DM, 0, 0, 0, 0);
    }

    // 3) logpQ, pK(+negent)
    logsoftmax_rows<<<Mrows, 256>>>(Qp);
    softmax_ent_rows<<<Mrows, 256>>>(Kp, negent);

    // 4) split logpQ/pK; transpose+split Vp
    run_split(Qp, lQh, lQl, (long long)Mrows * DM);
    run_split(Kp, pKh, pKl, (long long)Mrows * DM);
    {
        dim3 grid(DM / 32, NK / 32, BATCH);
        transpose_split_kernel<<<grid, dim3(32, 8)>>>(Vp, VpTh, VpTl);
    }

    // 5) scores[b,i,j] = logpQ_i . pK_j - negent[j]
    {
        dim3 grid(NK / 128, NQ / 128, BATCH);
        wm_gemm<2><<<grid, 256>>>(
            lQh, lQl, pKh, pKl, negent, attn, NQ, NK, DM,
            (long long)NQ * DM, (long long)NK * DM, (long long)NQ * NK, (long long)NK);
    }

    // 6) attn = softmax(scores)
    attn_softmax_rows<<<BATCH * NQ, 256>>>(attn);

    // 7) split attn
    run_split(attn, Ath, Atl, attnElems);

    // 8) out = attn @ Vp  (via VpT, NT form)
    {
        dim3 grid(DM / 128, NQ / 128, BATCH);
        wm_gemm<0><<<grid, 256>>>(
            Ath, Atl, VpTh, VpTl, nullptr, out, NQ, DM, NK,
            (long long)NQ * NK, (long long)DM * NK, (long long)NQ * DM, 0);
    }
}

// round 7
// speedup vs baseline: 2.2707x; 1.0350x over previous
#include <cuda_runtime.h>
#include <cuda_bf16.h>
#include <stdint.h>
#include <math.h>

// Problem constants
#define BATCH 4
#define NQ 2048
#define NK 2048
#define DM 1024

// ---------------------------------------------------------------------------
// Scratch (device globals: no allocation allowed)
// ---------------------------------------------------------------------------
__device__ float g_Qp[BATCH * NQ * DM];
__device__ float g_Kp[BATCH * NK * DM];
__device__ float g_Vp[BATCH * NK * DM];
__device__ float g_negent[BATCH * NK];
__device__ float g_attn[BATCH * NQ * NK];

__device__ __nv_bfloat16 g_Qh[BATCH * NQ * DM],  g_Ql[BATCH * NQ * DM];
__device__ __nv_bfloat16 g_Kh[BATCH * NK * DM],  g_Kl[BATCH * NK * DM];
__device__ __nv_bfloat16 g_Vh[BATCH * NK * DM],  g_Vl[BATCH * NK * DM];
__device__ __nv_bfloat16 g_Wqh[DM * DM], g_Wql[DM * DM];
__device__ __nv_bfloat16 g_Wkh[DM * DM], g_Wkl[DM * DM];
__device__ __nv_bfloat16 g_Wvh[DM * DM], g_Wvl[DM * DM];
__device__ __nv_bfloat16 g_lQh[BATCH * NQ * DM], g_lQl[BATCH * NQ * DM];
__device__ __nv_bfloat16 g_pKh[BATCH * NK * DM], g_pKl[BATCH * NK * DM];
__device__ __nv_bfloat16 g_VpTh[BATCH * DM * NK], g_VpTl[BATCH * DM * NK];
__device__ __nv_bfloat16 g_Ath[BATCH * NQ * NK], g_Atl[BATCH * NQ * NK];

// ---------------------------------------------------------------------------
// Warp-MMA split-bf16 GEMM: C[M,N] = A[M,K] @ B[N,K]^T  (NT), fp32 accumulate.
// A,B given as (hi, lo) bf16 pairs; computes Ah*Bh + Ah*Bl + Al*Bh.
// CTA tile 128x128, 8 warps of 64x32. K-chunk 32; all 4 tile variants loaded
// ONCE per chunk into a 3-stage cp.async pipeline; 3 term-MMA groups reuse
// register fragments. smem rows padded to 40 bf16 -> conflict-free ldmatrix.
// EPI: 0 none, 1 += vec[n], 2 -= vec[n].
// ---------------------------------------------------------------------------
#define KC 32
#define SROW 40
#define TILEE (128 * SROW)                       // elems per tile variant
#define GEMM_SMEM (3 * 4 * TILEE * 2)            // 3 stages x 4 variants, bytes

__device__ __forceinline__ void ldsm_x4(uint32_t* r, uint32_t addr) {
    asm volatile("ldmatrix.sync.aligned.m8n8.x4.shared.b16 {%0,%1,%2,%3}, [%4];"
                 : "=r"(r[0]), "=r"(r[1]), "=r"(r[2]), "=r"(r[3]) : "r"(addr));
}
__device__ __forceinline__ void mma_bf16(float* c, const uint32_t* a, uint32_t b0, uint32_t b1) {
    asm volatile(
        "mma.sync.aligned.m16n8k16.row.col.f32.bf16.bf16.f32 "
        "{%0,%1,%2,%3}, {%4,%5,%6,%7}, {%8,%9}, {%0,%1,%2,%3};"
        : "+f"(c[0]), "+f"(c[1]), "+f"(c[2]), "+f"(c[3])
        : "r"(a[0]), "r"(a[1]), "r"(a[2]), "r"(a[3]), "r"(b0), "r"(b1));
}

template<int EPI>
__global__ void __launch_bounds__(256)
wm_gemm(const __nv_bfloat16* __restrict__ Ah_, const __nv_bfloat16* __restrict__ Al_,
        const __nv_bfloat16* __restrict__ Bh_, const __nv_bfloat16* __restrict__ Bl_,
        const float* __restrict__ vec_, float* __restrict__ C_,
        int M, int N, int K,
        long long sA, long long sB, long long sC, long long sV)
{
    extern __shared__ __align__(16) __nv_bfloat16 smem[];

    const int tid = threadIdx.x, lane = tid & 31, wid = tid >> 5;
    const int m0 = blockIdx.y * 128, n0 = blockIdx.x * 128;
    const long long bz = blockIdx.z;
    const __nv_bfloat16* Ah = Ah_ + bz * sA;
    const __nv_bfloat16* Al = Al_ + bz * sA;
    const __nv_bfloat16* Bh = Bh_ + bz * sB;
    const __nv_bfloat16* Bl = Bl_ + bz * sB;
    float* C = C_ + bz * sC;
    const float* vec = (EPI != 0) ? (vec_ + bz * sV) : nullptr;

    const int m_warp = (wid >> 2) * 64;
    const int n_warp = (wid & 3) * 32;

    const int nt = K / KC;

    // loader: per variant, 256 threads x 2 segments x 16B = 128x32 bf16 tile
    const int lrow = tid >> 2;          // 0..63 (+64 second segment)
    const int lc   = (tid & 3) * 8;     // 0,8,16,24

    auto issue = [&](int c, int stage) {
        const int k0 = c * KC;
        __nv_bfloat16* sbase = smem + stage * 4 * TILEE;
        const __nv_bfloat16* srcs[4] = {Ah, Al, Bh, Bl};
        #pragma unroll
        for (int v = 0; v < 4; v++) {
            const __nv_bfloat16* src = srcs[v];
            const int g0 = (v < 2) ? m0 : n0;
            __nv_bfloat16* dstv = sbase + v * TILEE;
            #pragma unroll
            for (int i = 0; i < 2; i++) {
                const int row = lrow + i * 64;
                const void* g = src + (long long)(g0 + row) * K + k0 + lc;
                uint32_t d = (uint32_t)__cvta_generic_to_shared(dstv + row * SROW + lc);
                asm volatile("cp.async.cg.shared.global [%0], [%1], 16;" :: "r"(d), "l"(g));
            }
        }
        asm volatile("cp.async.commit_group;");
    };

    float acc[4][4][4];
    #pragma unroll
    for (int i = 0; i < 4; i++)
        #pragma unroll
        for (int j = 0; j < 4; j++)
            #pragma unroll
            for (int r = 0; r < 4; r++) acc[i][j][r] = 0.f;

    // ldmatrix per-thread row/col components
    const int ar  = lane & 15;
    const int ac8 = (lane >> 4) & 1;
    const int br  = (lane & 7) + ((lane & 16) ? 8 : 0);
    const int bc8 = (lane >> 3) & 1;

    issue(0, 0);
    if (nt > 1) issue(1, 1);
    if (nt > 2) issue(2, 2);

    for (int t = 0; t < nt; t++) {
        if (t + 3 <= nt)      { asm volatile("cp.async.wait_group 2;"); }
        else if (t + 2 == nt) { asm volatile("cp.async.wait_group 1;"); }
        else                  { asm volatile("cp.async.wait_group 0;"); }
        __syncthreads();

        const int stage = t % 3;
        const uint32_t sb = (uint32_t)__cvta_generic_to_shared(smem + stage * 4 * TILEE);
        const uint32_t ab_h = sb;
        const uint32_t ab_l = sb + TILEE * 2;
        const uint32_t bb_h = sb + 2 * TILEE * 2;
        const uint32_t bb_l = sb + 3 * TILEE * 2;

        #pragma unroll
        for (int k16 = 0; k16 < 2; k16++) {
            const int koff = (k16 * 16 + 0) * 2;
            uint32_t ah[4][4], bh[2][4];
            #pragma unroll
            for (int tm = 0; tm < 4; tm++)
                ldsm_x4(ah[tm], ab_h + ((m_warp + tm * 16 + ar) * SROW + k16 * 16 + ac8 * 8) * 2);
            #pragma unroll
            for (int p = 0; p < 2; p++)
                ldsm_x4(bh[p], bb_h + ((n_warp + p * 16 + br) * SROW + k16 * 16 + bc8 * 8) * 2);
            // term 0: Ah * Bh
            #pragma unroll
            for (int tm = 0; tm < 4; tm++)
                #pragma unroll
                for (int tn = 0; tn < 4; tn++)
                    mma_bf16(acc[tm][tn], ah[tm],
                             bh[tn >> 1][(tn & 1) * 2], bh[tn >> 1][(tn & 1) * 2 + 1]);
            // term 2: Al * Bh
            {
                uint32_t al[4][4];
                #pragma unroll
                for (int tm = 0; tm < 4; tm++)
                    ldsm_x4(al[tm], ab_l + ((m_warp + tm * 16 + ar) * SROW + k16 * 16 + ac8 * 8) * 2);
                #pragma unroll
                for (int tm = 0; tm < 4; tm++)
                    #pragma unroll
                    for (int tn = 0; tn < 4; tn++)
                        mma_bf16(acc[tm][tn], al[tm],
                                 bh[tn >> 1][(tn & 1) * 2], bh[tn >> 1][(tn & 1) * 2 + 1]);
            }
            // term 1: Ah * Bl
            {
                uint32_t bl[2][4];
                #pragma unroll
                for (int p = 0; p < 2; p++)
                    ldsm_x4(bl[p], bb_l + ((n_warp + p * 16 + br) * SROW + k16 * 16 + bc8 * 8) * 2);
                #pragma unroll
                for (int tm = 0; tm < 4; tm++)
                    #pragma unroll
                    for (int tn = 0; tn < 4; tn++)
                        mma_bf16(acc[tm][tn], ah[tm],
                                 bl[tn >> 1][(tn & 1) * 2], bl[tn >> 1][(tn & 1) * 2 + 1]);
            }
            (void)koff;
        }
        __syncthreads();
        if (t + 3 < nt) issue(t + 3, (t + 3) % 3);
    }

    // epilogue
    #pragma unroll
    for (int tm = 0; tm < 4; tm++) {
        #pragma unroll
        for (int tn = 0; tn < 4; tn++) {
            const int row = m0 + m_warp + tm * 16 + (lane >> 2);
            const int col = n0 + n_warp + tn * 8 + (lane & 3) * 2;
            float2 v0 = make_float2(acc[tm][tn][0], acc[tm][tn][1]);
            float2 v1 = make_float2(acc[tm][tn][2], acc[tm][tn][3]);
            if (EPI != 0) {
                const float2 vv = *(const float2*)&vec[col];
                if (EPI == 1) { v0.x += vv.x; v0.y += vv.y; v1.x += vv.x; v1.y += vv.y; }
                else          { v0.x -= vv.x; v0.y -= vv.y; v1.x -= vv.x; v1.y -= vv.y; }
            }
            *(float2*)&C[(long long)row * N + col] = v0;
            *(float2*)&C[(long long)(row + 8) * N + col] = v1;
        }
    }
}

// ---------------------------------------------------------------------------
// fp32 -> (bf16 hi, bf16 lo) split helpers
// ---------------------------------------------------------------------------
__device__ __forceinline__ void split1(float v, __nv_bfloat16& h, __nv_bfloat16& l) {
    h = __float2bfloat16(v);
    l = __float2bfloat16(v - __bfloat162float(h));
}

__global__ void __launch_bounds__(256) split_kernel(const float* __restrict__ x,
                                                    __nv_bfloat16* __restrict__ hi,
                                                    __nv_bfloat16* __restrict__ lo,
                                                    long long n4)
{
    const long long i = (long long)blockIdx.x * blockDim.x + threadIdx.x;
    if (i >= n4) return;
    const float4 v = ((const float4*)x)[i];
    __nv_bfloat16 h0, h1, h2, h3, l0, l1, l2, l3;
    split1(v.x, h0, l0); split1(v.y, h1, l1); split1(v.z, h2, l2); split1(v.w, h3, l3);
    __nv_bfloat162* H = (__nv_bfloat162*)hi;
    __nv_bfloat162* L = (__nv_bfloat162*)lo;
    H[2*i]   = __nv_bfloat162(h0, h1);
    H[2*i+1] = __nv_bfloat162(h2, h3);
    L[2*i]   = __nv_bfloat162(l0, l1);
    L[2*i+1] = __nv_bfloat162(l2, l3);
}

// Vp [b, 2048, 1024] fp32 -> VpT [b, 1024, 2048] split bf16
__global__ void __launch_bounds__(256) transpose_split_kernel(const float* __restrict__ src,
                                                              __nv_bfloat16* __restrict__ dhi,
                                                              __nv_bfloat16* __restrict__ dlo)
{
    __shared__ float tile[32][33];
    const long long b = blockIdx.z;
    const float* S = src + b * (long long)NK * DM;
    const int x0 = blockIdx.x * 32;
    const int y0 = blockIdx.y * 32;
    #pragma unroll
    for (int j = 0; j < 32; j += 8)
        tile[threadIdx.y + j][threadIdx.x] =
            S[(long long)(y0 + threadIdx.y + j) * DM + x0 + threadIdx.x];
    __syncthreads();
    __nv_bfloat16* Hh = dhi + b * (long long)DM * NK;
    __nv_bfloat16* Hl = dlo + b * (long long)DM * NK;
    #pragma unroll
    for (int j = 0; j < 32; j += 8) {
        const float v = tile[threadIdx.x][threadIdx.y + j];
        const int orow = x0 + threadIdx.y + j;
        const int ocol = y0 + threadIdx.x;
        __nv_bfloat16 h, l;
        split1(v, h, l);
        Hh[(long long)orow * NK + ocol] = h;
        Hl[(long long)orow * NK + ocol] = l;
    }
}

// ---------------------------------------------------------------------------
// Row reductions (fused with bf16 split outputs)
// ---------------------------------------------------------------------------
__device__ __forceinline__ float warp_max(float v) {
    #pragma unroll
    for (int o = 16; o; o >>= 1) v = fmaxf(v, __shfl_xor_sync(0xffffffffu, v, o));
    return v;
}
__device__ __forceinline__ float warp_sum(float v) {
    #pragma unroll
    for (int o = 16; o; o >>= 1) v += __shfl_xor_sync(0xffffffffu, v, o);
    return v;
}
__device__ __forceinline__ float block_reduce_max(float v, float* sred, int t) {
    v = warp_max(v);
    if ((t & 31) == 0) sred[t >> 5] = v;
    __syncthreads();
    if (t < 32) {
        float x = (t < 8) ? sred[t] : -INFINITY;
        #pragma unroll
        for (int o = 4; o; o >>= 1) x = fmaxf(x, __shfl_xor_sync(0xffffffffu, x, o));
        if (t == 0) sred[0] = x;
    }
    __syncthreads();
    const float r = sred[0];
    __syncthreads();
    return r;
}
__device__ __forceinline__ float block_reduce_sum(float v, float* sred, int t) {
    v = warp_sum(v);
    if ((t & 31) == 0) sred[t >> 5] = v;
    __syncthreads();
    if (t < 32) {
        float x = (t < 8) ? sred[t] : 0.f;
        #pragma unroll
        for (int o = 4; o; o >>= 1) x += __shfl_xor_sync(0xffffffffu, x, o);
        if (t == 0) sred[0] = x;
    }
    __syncthreads();
    const float r = sred[0];
    __syncthreads();
    return r;
}

// logpQ = log_softmax(Qp row); write split bf16 only. D = 1024
__global__ void __launch_bounds__(256)
logsoftmax_split_rows(const float* __restrict__ X,
                      __nv_bfloat16* __restrict__ Hh, __nv_bfloat16* __restrict__ Hl)
{
    const float* row = X + (size_t)blockIdx.x * DM;
    const int t = threadIdx.x;
    __shared__ float sred[8];
    float x[4];
    #pragma unroll
    for (int i = 0; i < 4; i++) x[i] = row[t + 256 * i];
    float m = fmaxf(fmaxf(x[0], x[1]), fmaxf(x[2], x[3]));
    m = block_reduce_max(m, sred, t);
    float s = 0.f;
    #pragma unroll
    for (int i = 0; i < 4; i++) s += expf(x[i] - m);
    s = block_reduce_sum(s, sred, t);
    const float lse = m + logf(s);
    const size_t base = (size_t)blockIdx.x * DM + t;
    #pragma unroll
    for (int i = 0; i < 4; i++) {
        __nv_bfloat16 h, l;
        split1(x[i] - lse, h, l);
        Hh[base + 256 * i] = h;
        Hl[base + 256 * i] = l;
    }
}

// pK = softmax(Kp row) split bf16; negent[row] = sum p*logp. D = 1024
__global__ void __launch_bounds__(256)
softmax_ent_split_rows(const float* __restrict__ X,
                       __nv_bfloat16* __restrict__ Hh, __nv_bfloat16* __restrict__ Hl,
                       float* __restrict__ negent)
{
    const float* row = X + (size_t)blockIdx.x * DM;
    const int t = threadIdx.x;
    __shared__ float sred[8];
    float x[4];
    #pragma unroll
    for (int i = 0; i < 4; i++) x[i] = row[t + 256 * i];
    float m = fmaxf(fmaxf(x[0], x[1]), fmaxf(x[2], x[3]));
    m = block_reduce_max(m, sred, t);
    float s = 0.f;
    #pragma unroll
    for (int i = 0; i < 4; i++) s += expf(x[i] - m);
    s = block_reduce_sum(s, sred, t);
    const float lse = m + logf(s);
    const size_t base = (size_t)blockIdx.x * DM + t;
    float se = 0.f;
    #pragma unroll
    for (int i = 0; i < 4; i++) {
        const float lp = x[i] - lse;
        const float p = expf(lp);
        se += p * lp;
        __nv_bfloat16 h, l;
        split1(p, h, l);
        Hh[base + 256 * i] = h;
        Hl[base + 256 * i] = l;
    }
    se = warp_sum(se);
    if ((t & 31) == 0) sred[t >> 5] = se;
    __syncthreads();
    if (t < 32) {
        float v = (t < 8) ? sred[t] : 0.f;
        #pragma unroll
        for (int o = 4; o; o >>= 1) v += __shfl_xor_sync(0xffffffffu, v, o);
        if (t == 0) negent[blockIdx.x] = v;
    }
}

// attn = softmax(scores row) in place (fp32) + split bf16. D = 2048
__global__ void __launch_bounds__(256)
attn_softmax_split_rows(float* __restrict__ X,
                        __nv_bfloat16* __restrict__ Hh, __nv_bfloat16* __restrict__ Hl)
{
    float* row = X + (size_t)blockIdx.x * NK;
    const int t = threadIdx.x;
    __shared__ float sred[8];
    float x[8];
    #pragma unroll
    for (int i = 0; i < 8; i++) x[i] = row[t + 256 * i];
    float m = -INFINITY;
    #pragma unroll
    for (int i = 0; i < 8; i++) m = fmaxf(m, x[i]);
    m = block_reduce_max(m, sred, t);
    float ex[8];
    float s = 0.f;
    #pragma unroll
    for (int i = 0; i < 8; i++) { ex[i] = expf(x[i] - m); s += ex[i]; }
    s = block_reduce_sum(s, sred, t);
    const float inv = 1.f / s;
    const size_t base = (size_t)blockIdx.x * NK + t;
    #pragma unroll
    for (int i = 0; i < 8; i++) {
        const float p = ex[i] * inv;
        row[t + 256 * i] = p;
        __nv_bfloat16 h, l;
        split1(p, h, l);
        Hh[base + 256 * i] = h;
        Hl[base + 256 * i] = l;
    }
}

// ---------------------------------------------------------------------------
// Launch
// ---------------------------------------------------------------------------
static void run_split(const float* x, __nv_bfloat16* hi, __nv_bfloat16* lo, long long n)
{
    const long long n4 = n >> 2;
    split_kernel<<<(unsigned)((n4 + 255) / 256), 256>>>(x, hi, lo, n4);
}

extern "C" void kernel_launch(void* const* d_in, const int* in_sizes, int n_in,
                              void* d_out, int out_size)
{
    const float* Q  = (const float*)d_in[0];
    const float* K  = (const float*)d_in[1];
    const float* V  = (const float*)d_in[2];
    const float* Wq = (const float*)d_in[3];
    const float* bq = (const float*)d_in[4];
    const float* Wk = (const float*)d_in[5];
    const float* bk = (const float*)d_in[6];
    const float* Wv = (const float*)d_in[7];
    const float* bv = (const float*)d_in[8];

    float* out = (float*)d_out;
    const long long outElems  = (long long)BATCH * NQ * DM;
    const long long attnElems = (long long)BATCH * NQ * NK;

    cudaFuncSetAttribute(wm_gemm<0>, cudaFuncAttributeMaxDynamicSharedMemorySize, GEMM_SMEM);
    cudaFuncSetAttribute(wm_gemm<1>, cudaFuncAttributeMaxDynamicSharedMemorySize, GEMM_SMEM);
    cudaFuncSetAttribute(wm_gemm<2>, cudaFuncAttributeMaxDynamicSharedMemorySize, GEMM_SMEM);

    float *Qp, *Kp, *Vp, *negent, *attn_scratch;
    cudaGetSymbolAddress((void**)&Qp, g_Qp);
    cudaGetSymbolAddress((void**)&Kp, g_Kp);
    cudaGetSymbolAddress((void**)&Vp, g_Vp);
    cudaGetSymbolAddress((void**)&negent, g_negent);
    cudaGetSymbolAddress((void**)&attn_scratch, g_attn);
    float* attn = ((long long)out_size >= outElems + attnElems) ? (out + outElems) : attn_scratch;

    __nv_bfloat16 *Qh, *Ql, *Kh, *Kl, *Vh, *Vl, *Wqh, *Wql, *Wkh, *Wkl, *Wvh, *Wvl;
    __nv_bfloat16 *lQh, *lQl, *pKh, *pKl, *VpTh, *VpTl, *Ath, *Atl;
    cudaGetSymbolAddress((void**)&Qh, g_Qh);   cudaGetSymbolAddress((void**)&Ql, g_Ql);
    cudaGetSymbolAddress((void**)&Kh, g_Kh);   cudaGetSymbolAddress((void**)&Kl, g_Kl);
    cudaGetSymbolAddress((void**)&Vh, g_Vh);   cudaGetSymbolAddress((void**)&Vl, g_Vl);
    cudaGetSymbolAddress((void**)&Wqh, g_Wqh); cudaGetSymbolAddress((void**)&Wql, g_Wql);
    cudaGetSymbolAddress((void**)&Wkh, g_Wkh); cudaGetSymbolAddress((void**)&Wkl, g_Wkl);
    cudaGetSymbolAddress((void**)&Wvh, g_Wvh); cudaGetSymbolAddress((void**)&Wvl, g_Wvl);
    cudaGetSymbolAddress((void**)&lQh, g_lQh); cudaGetSymbolAddress((void**)&lQl, g_lQl);
    cudaGetSymbolAddress((void**)&pKh, g_pKh); cudaGetSymbolAddress((void**)&pKl, g_pKl);
    cudaGetSymbolAddress((void**)&VpTh, g_VpTh); cudaGetSymbolAddress((void**)&VpTl, g_VpTl);
    cudaGetSymbolAddress((void**)&Ath, g_Ath); cudaGetSymbolAddress((void**)&Atl, g_Atl);

    const int Mrows = BATCH * NQ;  // 8192

    // 1) split inputs + weights to bf16 hi/lo
    run_split(Q, Qh, Ql, (long long)Mrows * DM);
    run_split(K, Kh, Kl, (long long)Mrows * DM);
    run_split(V, Vh, Vl, (long long)Mrows * DM);
    run_split(Wq, Wqh, Wql, (long long)DM * DM);
    run_split(Wk, Wkh, Wkl, (long long)DM * DM);
    run_split(Wv, Wvh, Wvl, (long long)DM * DM);

    // 2) projections: P = X @ W^T + b
    {
        dim3 grid(DM / 128, Mrows / 128, 1);
        wm_gemm<1><<<grid, 256, GEMM_SMEM>>>(Qh, Ql, Wqh, Wql, bq, Qp, Mrows, DM, DM, 0, 0, 0, 0);
        wm_gemm<1><<<grid, 256, GEMM_SMEM>>>(Kh, Kl, Wkh, Wkl, bk, Kp, Mrows, DM, DM, 0, 0, 0, 0);
        wm_gemm<1><<<grid, 256, GEMM_SMEM>>>(Vh, Vl, Wvh, Wvl, bv, Vp, Mrows, DM, DM, 0, 0, 0, 0);
    }

    // 3) fused: logpQ split, pK split + negent; transpose+split Vp
    logsoftmax_split_rows<<<Mrows, 256>>>(Qp, lQh, lQl);
    softmax_ent_split_rows<<<Mrows, 256>>>(Kp, pKh, pKl, negent);
    {
        dim3 grid(DM / 32, NK / 32, BATCH);
        transpose_split_kernel<<<grid, dim3(32, 8)>>>(Vp, VpTh, VpTl);
    }

    // 4) scores[b,i,j] = logpQ_i . pK_j - negent[j]
    {
        dim3 grid(NK / 128, NQ / 128, BATCH);
        wm_gemm<2><<<grid, 256, GEMM_SMEM>>>(
            lQh, lQl, pKh, pKl, negent, attn, NQ, NK, DM,
            (long long)NQ * DM, (long long)NK * DM, (long long)NQ * NK, (long long)NK);
    }

    // 5) attn = softmax(scores) fp32 + split bf16, one pass
    attn_softmax_split_rows<<<BATCH * NQ, 256>>>(attn, Ath, Atl);

    // 6) out = attn @ Vp (via VpT, NT form)
    {
        dim3 grid(DM / 128, NQ / 128, BATCH);
        wm_gemm<0><<<grid, 256, GEMM_SMEM>>>(
            Ath, Atl, VpTh, VpTl, nullptr, out, NQ, DM, NK,
            (long long)NQ * NK, (long long)DM * NK, (long long)NQ * DM, 0);
    }
}

// round 8
// speedup vs baseline: 2.5338x; 1.1159x over previous
#include <cuda_runtime.h>
#include <cuda_bf16.h>
#include <stdint.h>
#include <math.h>

// Problem constants
#define BATCH 4
#define NQ 2048
#define NK 2048
#define DM 1024

// ---------------------------------------------------------------------------
// Scratch (device globals: no allocation allowed)
// ---------------------------------------------------------------------------
__device__ float g_Qp[BATCH * NQ * DM];
__device__ float g_Kp[BATCH * NK * DM];
__device__ float g_Vp[BATCH * NK * DM];
__device__ float g_negent[BATCH * NK];
__device__ float g_attn[BATCH * NQ * NK];

__device__ __nv_bfloat16 g_Qh[BATCH * NQ * DM],  g_Ql[BATCH * NQ * DM];
__device__ __nv_bfloat16 g_Kh[BATCH * NK * DM],  g_Kl[BATCH * NK * DM];
__device__ __nv_bfloat16 g_Vh[BATCH * NK * DM],  g_Vl[BATCH * NK * DM];
__device__ __nv_bfloat16 g_Wqh[DM * DM], g_Wql[DM * DM];
__device__ __nv_bfloat16 g_Wkh[DM * DM], g_Wkl[DM * DM];
__device__ __nv_bfloat16 g_Wvh[DM * DM], g_Wvl[DM * DM];
__device__ __nv_bfloat16 g_lQh[BATCH * NQ * DM], g_lQl[BATCH * NQ * DM];
__device__ __nv_bfloat16 g_pKh[BATCH * NK * DM], g_pKl[BATCH * NK * DM];
__device__ __nv_bfloat16 g_VpTh[BATCH * DM * NK], g_VpTl[BATCH * DM * NK];
__device__ __nv_bfloat16 g_Ath[BATCH * NQ * NK], g_Atl[BATCH * NQ * NK];

// ---------------------------------------------------------------------------
// Warp-MMA split-bf16 GEMM: C[M,N] = A[M,K] @ B[N,K]^T  (NT), fp32 accumulate.
// Terms: Ah*Bh + Al*Bh + Ah*Bl. CTA tile 128x128, 8 warps of 64x32.
// K-chunk 32; 2-stage cp.async pipeline (80KB smem) -> 2 CTAs/SM for latency
// hiding. smem rows padded to 40 bf16 -> conflict-free ldmatrix.
// EPI: 0 none, 1 += vec[n], 2 -= vec[n].
// ---------------------------------------------------------------------------
#define KC 32
#define SROW 40
#define TILEE (128 * SROW)                       // elems per tile variant
#define GEMM_SMEM (2 * 4 * TILEE * 2)            // 2 stages x 4 variants, bytes

__device__ __forceinline__ void ldsm_x4(uint32_t* r, uint32_t addr) {
    asm volatile("ldmatrix.sync.aligned.m8n8.x4.shared.b16 {%0,%1,%2,%3}, [%4];"
                 : "=r"(r[0]), "=r"(r[1]), "=r"(r[2]), "=r"(r[3]) : "r"(addr));
}
__device__ __forceinline__ void mma_bf16(float* c, const uint32_t* a, uint32_t b0, uint32_t b1) {
    asm volatile(
        "mma.sync.aligned.m16n8k16.row.col.f32.bf16.bf16.f32 "
        "{%0,%1,%2,%3}, {%4,%5,%6,%7}, {%8,%9}, {%0,%1,%2,%3};"
        : "+f"(c[0]), "+f"(c[1]), "+f"(c[2]), "+f"(c[3])
        : "r"(a[0]), "r"(a[1]), "r"(a[2]), "r"(a[3]), "r"(b0), "r"(b1));
}

template<int EPI>
__global__ void __launch_bounds__(256, 2)
wm_gemm(const __nv_bfloat16* __restrict__ Ah_, const __nv_bfloat16* __restrict__ Al_,
        const __nv_bfloat16* __restrict__ Bh_, const __nv_bfloat16* __restrict__ Bl_,
        const float* __restrict__ vec_, float* __restrict__ C_,
        int M, int N, int K,
        long long sA, long long sB, long long sC, long long sV)
{
    extern __shared__ __align__(16) __nv_bfloat16 smem[];

    const int tid = threadIdx.x, lane = tid & 31, wid = tid >> 5;
    const int m0 = blockIdx.y * 128, n0 = blockIdx.x * 128;
    const long long bz = blockIdx.z;
    const __nv_bfloat16* Ah = Ah_ + bz * sA;
    const __nv_bfloat16* Al = Al_ + bz * sA;
    const __nv_bfloat16* Bh = Bh_ + bz * sB;
    const __nv_bfloat16* Bl = Bl_ + bz * sB;
    float* C = C_ + bz * sC;
    const float* vec = (EPI != 0) ? (vec_ + bz * sV) : nullptr;

    const int m_warp = (wid >> 2) * 64;
    const int n_warp = (wid & 3) * 32;

    const int nt = K / KC;

    // loader: per variant, 256 threads x 2 segments x 16B = 128x32 bf16 tile
    const int lrow = tid >> 2;          // 0..63 (+64 second segment)
    const int lc   = (tid & 3) * 8;     // 0,8,16,24

    auto issue = [&](int c, int stage) {
        const int k0 = c * KC;
        __nv_bfloat16* sbase = smem + stage * 4 * TILEE;
        const __nv_bfloat16* srcs[4] = {Ah, Al, Bh, Bl};
        #pragma unroll
        for (int v = 0; v < 4; v++) {
            const __nv_bfloat16* src = srcs[v];
            const int g0 = (v < 2) ? m0 : n0;
            __nv_bfloat16* dstv = sbase + v * TILEE;
            #pragma unroll
            for (int i = 0; i < 2; i++) {
                const int row = lrow + i * 64;
                const void* g = src + (long long)(g0 + row) * K + k0 + lc;
                uint32_t d = (uint32_t)__cvta_generic_to_shared(dstv + row * SROW + lc);
                asm volatile("cp.async.cg.shared.global [%0], [%1], 16;" :: "r"(d), "l"(g));
            }
        }
        asm volatile("cp.async.commit_group;");
    };

    float acc[4][4][4];
    #pragma unroll
    for (int i = 0; i < 4; i++)
        #pragma unroll
        for (int j = 0; j < 4; j++)
            #pragma unroll
            for (int r = 0; r < 4; r++) acc[i][j][r] = 0.f;

    // ldmatrix per-thread row/col components
    const int ar  = lane & 15;
    const int ac8 = (lane >> 4) & 1;
    const int br  = (lane & 7) + ((lane & 16) ? 8 : 0);
    const int bc8 = (lane >> 3) & 1;

    issue(0, 0);
    if (nt > 1) issue(1, 1);

    for (int t = 0; t < nt; t++) {
        if (t + 1 < nt) { asm volatile("cp.async.wait_group 1;"); }
        else            { asm volatile("cp.async.wait_group 0;"); }
        __syncthreads();

        const int stage = t & 1;
        const uint32_t sb = (uint32_t)__cvta_generic_to_shared(smem + stage * 4 * TILEE);
        const uint32_t ab_h = sb;
        const uint32_t ab_l = sb + TILEE * 2;
        const uint32_t bb_h = sb + 2 * TILEE * 2;
        const uint32_t bb_l = sb + 3 * TILEE * 2;

        #pragma unroll
        for (int k16 = 0; k16 < 2; k16++) {
            uint32_t ah[4][4], bh[2][4];
            #pragma unroll
            for (int tm = 0; tm < 4; tm++)
                ldsm_x4(ah[tm], ab_h + ((m_warp + tm * 16 + ar) * SROW + k16 * 16 + ac8 * 8) * 2);
            #pragma unroll
            for (int p = 0; p < 2; p++)
                ldsm_x4(bh[p], bb_h + ((n_warp + p * 16 + br) * SROW + k16 * 16 + bc8 * 8) * 2);
            // term 0: Ah * Bh
            #pragma unroll
            for (int tm = 0; tm < 4; tm++)
                #pragma unroll
                for (int tn = 0; tn < 4; tn++)
                    mma_bf16(acc[tm][tn], ah[tm],
                             bh[tn >> 1][(tn & 1) * 2], bh[tn >> 1][(tn & 1) * 2 + 1]);
            // term 1: Al * Bh (then Al dies)
            {
                uint32_t al[4][4];
                #pragma unroll
                for (int tm = 0; tm < 4; tm++)
                    ldsm_x4(al[tm], ab_l + ((m_warp + tm * 16 + ar) * SROW + k16 * 16 + ac8 * 8) * 2);
                #pragma unroll
                for (int tm = 0; tm < 4; tm++)
                    #pragma unroll
                    for (int tn = 0; tn < 4; tn++)
                        mma_bf16(acc[tm][tn], al[tm],
                                 bh[tn >> 1][(tn & 1) * 2], bh[tn >> 1][(tn & 1) * 2 + 1]);
            }
            // term 2: Ah * Bl
            {
                uint32_t bl[2][4];
                #pragma unroll
                for (int p = 0; p < 2; p++)
                    ldsm_x4(bl[p], bb_l + ((n_warp + p * 16 + br) * SROW + k16 * 16 + bc8 * 8) * 2);
                #pragma unroll
                for (int tm = 0; tm < 4; tm++)
                    #pragma unroll
                    for (int tn = 0; tn < 4; tn++)
                        mma_bf16(acc[tm][tn], ah[tm],
                                 bl[tn >> 1][(tn & 1) * 2], bl[tn >> 1][(tn & 1) * 2 + 1]);
            }
        }
        __syncthreads();
        if (t + 2 < nt) issue(t + 2, stage);
    }

    // epilogue
    #pragma unroll
    for (int tm = 0; tm < 4; tm++) {
        #pragma unroll
        for (int tn = 0; tn < 4; tn++) {
            const int row = m0 + m_warp + tm * 16 + (lane >> 2);
            const int col = n0 + n_warp + tn * 8 + (lane & 3) * 2;
            float2 v0 = make_float2(acc[tm][tn][0], acc[tm][tn][1]);
            float2 v1 = make_float2(acc[tm][tn][2], acc[tm][tn][3]);
            if (EPI != 0) {
                const float2 vv = *(const float2*)&vec[col];
                if (EPI == 1) { v0.x += vv.x; v0.y += vv.y; v1.x += vv.x; v1.y += vv.y; }
                else          { v0.x -= vv.x; v0.y -= vv.y; v1.x -= vv.x; v1.y -= vv.y; }
            }
            *(float2*)&C[(long long)row * N + col] = v0;
            *(float2*)&C[(long long)(row + 8) * N + col] = v1;
        }
    }
}

// ---------------------------------------------------------------------------
// fp32 -> (bf16 hi, bf16 lo) split helpers
// ---------------------------------------------------------------------------
__device__ __forceinline__ void split1(float v, __nv_bfloat16& h, __nv_bfloat16& l) {
    h = __float2bfloat16(v);
    l = __float2bfloat16(v - __bfloat162float(h));
}

__global__ void __launch_bounds__(256) split_kernel(const float* __restrict__ x,
                                                    __nv_bfloat16* __restrict__ hi,
                                                    __nv_bfloat16* __restrict__ lo,
                                                    long long n4)
{
    const long long i = (long long)blockIdx.x * blockDim.x + threadIdx.x;
    if (i >= n4) return;
    const float4 v = ((const float4*)x)[i];
    __nv_bfloat16 h0, h1, h2, h3, l0, l1, l2, l3;
    split1(v.x, h0, l0); split1(v.y, h1, l1); split1(v.z, h2, l2); split1(v.w, h3, l3);
    __nv_bfloat162* H = (__nv_bfloat162*)hi;
    __nv_bfloat162* L = (__nv_bfloat162*)lo;
    H[2*i]   = __nv_bfloat162(h0, h1);
    H[2*i+1] = __nv_bfloat162(h2, h3);
    L[2*i]   = __nv_bfloat162(l0, l1);
    L[2*i+1] = __nv_bfloat162(l2, l3);
}

// Vp [b, 2048, 1024] fp32 -> VpT [b, 1024, 2048] split bf16
__global__ void __launch_bounds__(256) transpose_split_kernel(const float* __restrict__ src,
                                                              __nv_bfloat16* __restrict__ dhi,
                                                              __nv_bfloat16* __restrict__ dlo)
{
    __shared__ float tile[32][33];
    const long long b = blockIdx.z;
    const float* S = src + b * (long long)NK * DM;
    const int x0 = blockIdx.x * 32;
    const int y0 = blockIdx.y * 32;
    #pragma unroll
    for (int j = 0; j < 32; j += 8)
        tile[threadIdx.y + j][threadIdx.x] =
            S[(long long)(y0 + threadIdx.y + j) * DM + x0 + threadIdx.x];
    __syncthreads();
    __nv_bfloat16* Hh = dhi + b * (long long)DM * NK;
    __nv_bfloat16* Hl = dlo + b * (long long)DM * NK;
    #pragma unroll
    for (int j = 0; j < 32; j += 8) {
        const float v = tile[threadIdx.x][threadIdx.y + j];
        const int orow = x0 + threadIdx.y + j;
        const int ocol = y0 + threadIdx.x;
        __nv_bfloat16 h, l;
        split1(v, h, l);
        Hh[(long long)orow * NK + ocol] = h;
        Hl[(long long)orow * NK + ocol] = l;
    }
}

// ---------------------------------------------------------------------------
// Row reductions (fused with bf16 split outputs)
// ---------------------------------------------------------------------------
__device__ __forceinline__ float warp_max(float v) {
    #pragma unroll
    for (int o = 16; o; o >>= 1) v = fmaxf(v, __shfl_xor_sync(0xffffffffu, v, o));
    return v;
}
__device__ __forceinline__ float warp_sum(float v) {
    #pragma unroll
    for (int o = 16; o; o >>= 1) v += __shfl_xor_sync(0xffffffffu, v, o);
    return v;
}
__device__ __forceinline__ float block_reduce_max(float v, float* sred, int t) {
    v = warp_max(v);
    if ((t & 31) == 0) sred[t >> 5] = v;
    __syncthreads();
    if (t < 32) {
        float x = (t < 8) ? sred[t] : -INFINITY;
        #pragma unroll
        for (int o = 4; o; o >>= 1) x = fmaxf(x, __shfl_xor_sync(0xffffffffu, x, o));
        if (t == 0) sred[0] = x;
    }
    __syncthreads();
    const float r = sred[0];
    __syncthreads();
    return r;
}
__device__ __forceinline__ float block_reduce_sum(float v, float* sred, int t) {
    v = warp_sum(v);
    if ((t & 31) == 0) sred[t >> 5] = v;
    __syncthreads();
    if (t < 32) {
        float x = (t < 8) ? sred[t] : 0.f;
        #pragma unroll
        for (int o = 4; o; o >>= 1) x += __shfl_xor_sync(0xffffffffu, x, o);
        if (t == 0) sred[0] = x;
    }
    __syncthreads();
    const float r = sred[0];
    __syncthreads();
    return r;
}

// logpQ = log_softmax(Qp row); write split bf16 only. D = 1024
__global__ void __launch_bounds__(256)
logsoftmax_split_rows(const float* __restrict__ X,
                      __nv_bfloat16* __restrict__ Hh, __nv_bfloat16* __restrict__ Hl)
{
    const float* row = X + (size_t)blockIdx.x * DM;
    const int t = threadIdx.x;
    __shared__ float sred[8];
    float x[4];
    #pragma unroll
    for (int i = 0; i < 4; i++) x[i] = row[t + 256 * i];
    float m = fmaxf(fmaxf(x[0], x[1]), fmaxf(x[2], x[3]));
    m = block_reduce_max(m, sred, t);
    float s = 0.f;
    #pragma unroll
    for (int i = 0; i < 4; i++) s += expf(x[i] - m);
    s = block_reduce_sum(s, sred, t);
    const float lse = m + logf(s);
    const size_t base = (size_t)blockIdx.x * DM + t;
    #pragma unroll
    for (int i = 0; i < 4; i++) {
        __nv_bfloat16 h, l;
        split1(x[i] - lse, h, l);
        Hh[base + 256 * i] = h;
        Hl[base + 256 * i] = l;
    }
}

// pK = softmax(Kp row) split bf16; negent[row] = sum p*logp. D = 1024
__global__ void __launch_bounds__(256)
softmax_ent_split_rows(const float* __restrict__ X,
                       __nv_bfloat16* __restrict__ Hh, __nv_bfloat16* __restrict__ Hl,
                       float* __restrict__ negent)
{
    const float* row = X + (size_t)blockIdx.x * DM;
    const int t = threadIdx.x;
    __shared__ float sred[8];
    float x[4];
    #pragma unroll
    for (int i = 0; i < 4; i++) x[i] = row[t + 256 * i];
    float m = fmaxf(fmaxf(x[0], x[1]), fmaxf(x[2], x[3]));
    m = block_reduce_max(m, sred, t);
    float s = 0.f;
    #pragma unroll
    for (int i = 0; i < 4; i++) s += expf(x[i] - m);
    s = block_reduce_sum(s, sred, t);
    const float lse = m + logf(s);
    const size_t base = (size_t)blockIdx.x * DM + t;
    float se = 0.f;
    #pragma unroll
    for (int i = 0; i < 4; i++) {
        const float lp = x[i] - lse;
        const float p = expf(lp);
        se += p * lp;
        __nv_bfloat16 h, l;
        split1(p, h, l);
        Hh[base + 256 * i] = h;
        Hl[base + 256 * i] = l;
    }
    se = warp_sum(se);
    if ((t & 31) == 0) sred[t >> 5] = se;
    __syncthreads();
    if (t < 32) {
        float v = (t < 8) ? sred[t] : 0.f;
        #pragma unroll
        for (int o = 4; o; o >>= 1) v += __shfl_xor_sync(0xffffffffu, v, o);
        if (t == 0) negent[blockIdx.x] = v;
    }
}

// attn = softmax(scores row) in place (fp32) + split bf16. D = 2048
__global__ void __launch_bounds__(256)
attn_softmax_split_rows(float* __restrict__ X,
                        __nv_bfloat16* __restrict__ Hh, __nv_bfloat16* __restrict__ Hl)
{
    float* row = X + (size_t)blockIdx.x * NK;
    const int t = threadIdx.x;
    __shared__ float sred[8];
    float x[8];
    #pragma unroll
    for (int i = 0; i < 8; i++) x[i] = row[t + 256 * i];
    float m = -INFINITY;
    #pragma unroll
    for (int i = 0; i < 8; i++) m = fmaxf(m, x[i]);
    m = block_reduce_max(m, sred, t);
    float ex[8];
    float s = 0.f;
    #pragma unroll
    for (int i = 0; i < 8; i++) { ex[i] = expf(x[i] - m); s += ex[i]; }
    s = block_reduce_sum(s, sred, t);
    const float inv = 1.f / s;
    const size_t base = (size_t)blockIdx.x * NK + t;
    #pragma unroll
    for (int i = 0; i < 8; i++) {
        const float p = ex[i] * inv;
        row[t + 256 * i] = p;
        __nv_bfloat16 h, l;
        split1(p, h, l);
        Hh[base + 256 * i] = h;
        Hl[base + 256 * i] = l;
    }
}

// ---------------------------------------------------------------------------
// Launch
// ---------------------------------------------------------------------------
static void run_split(const float* x, __nv_bfloat16* hi, __nv_bfloat16* lo, long long n)
{
    const long long n4 = n >> 2;
    split_kernel<<<(unsigned)((n4 + 255) / 256), 256>>>(x, hi, lo, n4);
}

extern "C" void kernel_launch(void* const* d_in, const int* in_sizes, int n_in,
                              void* d_out, int out_size)
{
    const float* Q  = (const float*)d_in[0];
    const float* K  = (const float*)d_in[1];
    const float* V  = (const float*)d_in[2];
    const float* Wq = (const float*)d_in[3];
    const float* bq = (const float*)d_in[4];
    const float* Wk = (const float*)d_in[5];
    const float* bk = (const float*)d_in[6];
    const float* Wv = (const float*)d_in[7];
    const float* bv = (const float*)d_in[8];

    float* out = (float*)d_out;
    const long long outElems  = (long long)BATCH * NQ * DM;
    const long long attnElems = (long long)BATCH * NQ * NK;

    cudaFuncSetAttribute(wm_gemm<0>, cudaFuncAttributeMaxDynamicSharedMemorySize, GEMM_SMEM);
    cudaFuncSetAttribute(wm_gemm<1>, cudaFuncAttributeMaxDynamicSharedMemorySize, GEMM_SMEM);
    cudaFuncSetAttribute(wm_gemm<2>, cudaFuncAttributeMaxDynamicSharedMemorySize, GEMM_SMEM);

    float *Qp, *Kp, *Vp, *negent, *attn_scratch;
    cudaGetSymbolAddress((void**)&Qp, g_Qp);
    cudaGetSymbolAddress((void**)&Kp, g_Kp);
    cudaGetSymbolAddress((void**)&Vp, g_Vp);
    cudaGetSymbolAddress((void**)&negent, g_negent);
    cudaGetSymbolAddress((void**)&attn_scratch, g_attn);
    float* attn = ((long long)out_size >= outElems + attnElems) ? (out + outElems) : attn_scratch;

    __nv_bfloat16 *Qh, *Ql, *Kh, *Kl, *Vh, *Vl, *Wqh, *Wql, *Wkh, *Wkl, *Wvh, *Wvl;
    __nv_bfloat16 *lQh, *lQl, *pKh, *pKl, *VpTh, *VpTl, *Ath, *Atl;
    cudaGetSymbolAddress((void**)&Qh, g_Qh);   cudaGetSymbolAddress((void**)&Ql, g_Ql);
    cudaGetSymbolAddress((void**)&Kh, g_Kh);   cudaGetSymbolAddress((void**)&Kl, g_Kl);
    cudaGetSymbolAddress((void**)&Vh, g_Vh);   cudaGetSymbolAddress((void**)&Vl, g_Vl);
    cudaGetSymbolAddress((void**)&Wqh, g_Wqh); cudaGetSymbolAddress((void**)&Wql, g_Wql);
    cudaGetSymbolAddress((void**)&Wkh, g_Wkh); cudaGetSymbolAddress((void**)&Wkl, g_Wkl);
    cudaGetSymbolAddress((void**)&Wvh, g_Wvh); cudaGetSymbolAddress((void**)&Wvl, g_Wvl);
    cudaGetSymbolAddress((void**)&lQh, g_lQh); cudaGetSymbolAddress((void**)&lQl, g_lQl);
    cudaGetSymbolAddress((void**)&pKh, g_pKh); cudaGetSymbolAddress((void**)&pKl, g_pKl);
    cudaGetSymbolAddress((void**)&VpTh, g_VpTh); cudaGetSymbolAddress((void**)&VpTl, g_VpTl);
    cudaGetSymbolAddress((void**)&Ath, g_Ath); cudaGetSymbolAddress((void**)&Atl, g_Atl);

    const int Mrows = BATCH * NQ;  // 8192

    // 1) split inputs + weights to bf16 hi/lo
    run_split(Q, Qh, Ql, (long long)Mrows * DM);
    run_split(K, Kh, Kl, (long long)Mrows * DM);
    run_split(V, Vh, Vl, (long long)Mrows * DM);
    run_split(Wq, Wqh, Wql, (long long)DM * DM);
    run_split(Wk, Wkh, Wkl, (long long)DM * DM);
    run_split(Wv, Wvh, Wvl, (long long)DM * DM);

    // 2) projections: P = X @ W^T + b
    {
        dim3 grid(DM / 128, Mrows / 128, 1);
        wm_gemm<1><<<grid, 256, GEMM_SMEM>>>(Qh, Ql, Wqh, Wql, bq, Qp, Mrows, DM, DM, 0, 0, 0, 0);
        wm_gemm<1><<<grid, 256, GEMM_SMEM>>>(Kh, Kl, Wkh, Wkl, bk, Kp, Mrows, DM, DM, 0, 0, 0, 0);
        wm_gemm<1><<<grid, 256, GEMM_SMEM>>>(Vh, Vl, Wvh, Wvl, bv, Vp, Mrows, DM, DM, 0, 0, 0, 0);
    }

    // 3) fused: logpQ split, pK split + negent; transpose+split Vp
    logsoftmax_split_rows<<<Mrows, 256>>>(Qp, lQh, lQl);
    softmax_ent_split_rows<<<Mrows, 256>>>(Kp, pKh, pKl, negent);
    {
        dim3 grid(DM / 32, NK / 32, BATCH);
        transpose_split_kernel<<<grid, dim3(32, 8)>>>(Vp, VpTh, VpTl);
    }

    // 4) scores[b,i,j] = logpQ_i . pK_j - negent[j]
    {
        dim3 grid(NK / 128, NQ / 128, BATCH);
        wm_gemm<2><<<grid, 256, GEMM_SMEM>>>(
            lQh, lQl, pKh, pKl, negent, attn, NQ, NK, DM,
            (long long)NQ * DM, (long long)NK * DM, (long long)NQ * NK, (long long)NK);
    }

    // 5) attn = softmax(scores) fp32 + split bf16, one pass
    attn_softmax_split_rows<<<BATCH * NQ, 256>>>(attn, Ath, Atl);

    // 6) out = attn @ Vp (via VpT, NT form)
    {
        dim3 grid(DM / 128, NQ / 128, BATCH);
        wm_gemm<0><<<grid, 256, GEMM_SMEM>>>(
            Ath, Atl, VpTh, VpTl, nullptr, out, NQ, DM, NK,
            (long long)NQ * NK, (long long)DM * NK, (long long)NQ * DM, 0);
    }
}

// round 9
// speedup vs baseline: 2.7282x; 1.0767x over previous
#include <cuda_runtime.h>
#include <cuda_bf16.h>
#include <stdint.h>
#include <math.h>

// Problem constants
#define BATCH 4
#define NQ 2048
#define NK 2048
#define DM 1024

// ---------------------------------------------------------------------------
// Scratch (device globals)
// ---------------------------------------------------------------------------
__device__ float g_Kp[BATCH * NK * DM];
__device__ float g_Vp[BATCH * NK * DM];
__device__ float g_negent[BATCH * NK];
__device__ float g_attn[BATCH * NQ * NK];

__device__ __nv_bfloat16 g_Qh[BATCH * NQ * DM],  g_Ql[BATCH * NQ * DM];
__device__ __nv_bfloat16 g_Kh[BATCH * NK * DM],  g_Kl[BATCH * NK * DM];
__device__ __nv_bfloat16 g_Vh[BATCH * NK * DM],  g_Vl[BATCH * NK * DM];
__device__ __nv_bfloat16 g_Wqh[DM * DM], g_Wql[DM * DM];
__device__ __nv_bfloat16 g_Wkh[DM * DM], g_Wkl[DM * DM];
__device__ __nv_bfloat16 g_Wvh[DM * DM], g_Wvl[DM * DM];
__device__ __nv_bfloat16 g_Qph[BATCH * NQ * DM], g_Qpl[BATCH * NQ * DM];  // split Qp (post-proj)
__device__ __nv_bfloat16 g_pKh[BATCH * NK * DM], g_pKl[BATCH * NK * DM];
__device__ __nv_bfloat16 g_VpTh[BATCH * DM * NK], g_VpTl[BATCH * DM * NK];
__device__ __nv_bfloat16 g_Ath[BATCH * NQ * NK], g_Atl[BATCH * NQ * NK];

// ---------------------------------------------------------------------------
// Common MMA helpers
// ---------------------------------------------------------------------------
#define KC 32
#define SROW 40
#define TILEE (128 * SROW)
#define GEMM_SMEM (2 * 4 * TILEE * 2)            // 2 stages x 4 variants, bytes

__device__ __forceinline__ void ldsm_x4(uint32_t* r, uint32_t addr) {
    asm volatile("ldmatrix.sync.aligned.m8n8.x4.shared.b16 {%0,%1,%2,%3}, [%4];"
                 : "=r"(r[0]), "=r"(r[1]), "=r"(r[2]), "=r"(r[3]) : "r"(addr));
}
__device__ __forceinline__ void mma_bf16(float* c, const uint32_t* a, uint32_t b0, uint32_t b1) {
    asm volatile(
        "mma.sync.aligned.m16n8k16.row.col.f32.bf16.bf16.f32 "
        "{%0,%1,%2,%3}, {%4,%5,%6,%7}, {%8,%9}, {%0,%1,%2,%3};"
        : "+f"(c[0]), "+f"(c[1]), "+f"(c[2]), "+f"(c[3])
        : "r"(a[0]), "r"(a[1]), "r"(a[2]), "r"(a[3]), "r"(b0), "r"(b1));
}
__device__ __forceinline__ void split1(float v, __nv_bfloat16& h, __nv_bfloat16& l) {
    h = __float2bfloat16(v);
    l = __float2bfloat16(v - __bfloat162float(h));
}

// ---------------------------------------------------------------------------
// Mainloop macro-body (shared by both GEMM kernels).
// Computes acc = Ah*Bh + Al*Bh + Ah*Bl over K, for the CTA tile (m0,n0).
// ---------------------------------------------------------------------------
struct GemmCore {
    const __nv_bfloat16 *Ah, *Al, *Bh, *Bl;
    int m0, n0, K;

    template<typename SmemT>
    __device__ __forceinline__ void run(SmemT* smem, float acc[4][4][4],
                                        int tid, int lane, int wid) const
    {
        const int m_warp = (wid >> 2) * 64;
        const int n_warp = (wid & 3) * 32;
        const int nt = K / KC;
        const int lrow = tid >> 2;
        const int lc   = (tid & 3) * 8;

        auto issue = [&](int c, int stage) {
            const int k0 = c * KC;
            __nv_bfloat16* sbase = smem + stage * 4 * TILEE;
            const __nv_bfloat16* srcs[4] = {Ah, Al, Bh, Bl};
            #pragma unroll
            for (int v = 0; v < 4; v++) {
                const __nv_bfloat16* src = srcs[v];
                const int g0 = (v < 2) ? m0 : n0;
                __nv_bfloat16* dstv = sbase + v * TILEE;
                #pragma unroll
                for (int i = 0; i < 2; i++) {
                    const int row = lrow + i * 64;
                    const void* g = src + (long long)(g0 + row) * K + k0 + lc;
                    uint32_t d = (uint32_t)__cvta_generic_to_shared(dstv + row * SROW + lc);
                    asm volatile("cp.async.cg.shared.global [%0], [%1], 16;" :: "r"(d), "l"(g));
                }
            }
            asm volatile("cp.async.commit_group;");
        };

        const int ar  = lane & 15;
        const int ac8 = (lane >> 4) & 1;
        const int br  = (lane & 7) + ((lane & 16) ? 8 : 0);
        const int bc8 = (lane >> 3) & 1;

        issue(0, 0);
        if (nt > 1) issue(1, 1);

        for (int t = 0; t < nt; t++) {
            if (t + 1 < nt) { asm volatile("cp.async.wait_group 1;"); }
            else            { asm volatile("cp.async.wait_group 0;"); }
            __syncthreads();

            const int stage = t & 1;
            const uint32_t sb = (uint32_t)__cvta_generic_to_shared(smem + stage * 4 * TILEE);
            const uint32_t ab_h = sb;
            const uint32_t ab_l = sb + TILEE * 2;
            const uint32_t bb_h = sb + 2 * TILEE * 2;
            const uint32_t bb_l = sb + 3 * TILEE * 2;

            #pragma unroll
            for (int k16 = 0; k16 < 2; k16++) {
                uint32_t ah[4][4], bh[2][4];
                #pragma unroll
                for (int tm = 0; tm < 4; tm++)
                    ldsm_x4(ah[tm], ab_h + ((m_warp + tm * 16 + ar) * SROW + k16 * 16 + ac8 * 8) * 2);
                #pragma unroll
                for (int p = 0; p < 2; p++)
                    ldsm_x4(bh[p], bb_h + ((n_warp + p * 16 + br) * SROW + k16 * 16 + bc8 * 8) * 2);
                #pragma unroll
                for (int tm = 0; tm < 4; tm++)
                    #pragma unroll
                    for (int tn = 0; tn < 4; tn++)
                        mma_bf16(acc[tm][tn], ah[tm],
                                 bh[tn >> 1][(tn & 1) * 2], bh[tn >> 1][(tn & 1) * 2 + 1]);
                {
                    uint32_t al[4][4];
                    #pragma unroll
                    for (int tm = 0; tm < 4; tm++)
                        ldsm_x4(al[tm], ab_l + ((m_warp + tm * 16 + ar) * SROW + k16 * 16 + ac8 * 8) * 2);
                    #pragma unroll
                    for (int tm = 0; tm < 4; tm++)
                        #pragma unroll
                        for (int tn = 0; tn < 4; tn++)
                            mma_bf16(acc[tm][tn], al[tm],
                                     bh[tn >> 1][(tn & 1) * 2], bh[tn >> 1][(tn & 1) * 2 + 1]);
                }
                {
                    uint32_t bl[2][4];
                    #pragma unroll
                    for (int p = 0; p < 2; p++)
                        ldsm_x4(bl[p], bb_l + ((n_warp + p * 16 + br) * SROW + k16 * 16 + bc8 * 8) * 2);
                    #pragma unroll
                    for (int tm = 0; tm < 4; tm++)
                        #pragma unroll
                        for (int tn = 0; tn < 4; tn++)
                            mma_bf16(acc[tm][tn], ah[tm],
                                     bl[tn >> 1][(tn & 1) * 2], bl[tn >> 1][(tn & 1) * 2 + 1]);
                }
            }
            __syncthreads();
            if (t + 2 < nt) issue(t + 2, stage);
        }
    }
};

// ---------------------------------------------------------------------------
// Generic GEMM (scores / out). EPI: 0 none, 2 -= vec[n]. NT form, batched.
// ---------------------------------------------------------------------------
template<int EPI>
__global__ void __launch_bounds__(256, 2)
wm_gemm(const __nv_bfloat16* __restrict__ Ah_, const __nv_bfloat16* __restrict__ Al_,
        const __nv_bfloat16* __restrict__ Bh_, const __nv_bfloat16* __restrict__ Bl_,
        const float* __restrict__ vec_, float* __restrict__ C_,
        int M, int N, int K,
        long long sA, long long sB, long long sC, long long sV)
{
    extern __shared__ __align__(16) __nv_bfloat16 smem[];
    const int tid = threadIdx.x, lane = tid & 31, wid = tid >> 5;
    const long long bz = blockIdx.z;

    GemmCore core;
    core.Ah = Ah_ + bz * sA; core.Al = Al_ + bz * sA;
    core.Bh = Bh_ + bz * sB; core.Bl = Bl_ + bz * sB;
    core.m0 = blockIdx.y * 128; core.n0 = blockIdx.x * 128; core.K = K;
    float* C = C_ + bz * sC;
    const float* vec = (EPI != 0) ? (vec_ + bz * sV) : nullptr;

    float acc[4][4][4];
    #pragma unroll
    for (int i = 0; i < 4; i++)
        #pragma unroll
        for (int j = 0; j < 4; j++)
            #pragma unroll
            for (int r = 0; r < 4; r++) acc[i][j][r] = 0.f;

    core.run(smem, acc, tid, lane, wid);

    const int m_warp = (wid >> 2) * 64;
    const int n_warp = (wid & 3) * 32;
    #pragma unroll
    for (int tm = 0; tm < 4; tm++) {
        #pragma unroll
        for (int tn = 0; tn < 4; tn++) {
            const int row = core.m0 + m_warp + tm * 16 + (lane >> 2);
            const int col = core.n0 + n_warp + tn * 8 + (lane & 3) * 2;
            float2 v0 = make_float2(acc[tm][tn][0], acc[tm][tn][1]);
            float2 v1 = make_float2(acc[tm][tn][2], acc[tm][tn][3]);
            if (EPI == 2) {
                const float2 vv = *(const float2*)&vec[col];
                v0.x -= vv.x; v0.y -= vv.y; v1.x -= vv.x; v1.y -= vv.y;
            }
            *(float2*)&C[(long long)row * N + col] = v0;
            *(float2*)&C[(long long)(row + 8) * N + col] = v1;
        }
    }
}

// ---------------------------------------------------------------------------
// Merged projection GEMM: grid.z selects {Q, K, V}. P = X @ W^T + b.
//   z=0 (Q): write split bf16 hi/lo only (scores use Qp directly — the
//            log-softmax row shift is softmax-invariant and negent handles
//            the column term).
//   z=1 (K), z=2 (V): write fp32 (consumed by softmax_ent / transpose).
// ---------------------------------------------------------------------------
__global__ void __launch_bounds__(256, 2)
proj_gemm(const __nv_bfloat16* __restrict__ Qh, const __nv_bfloat16* __restrict__ Ql,
          const __nv_bfloat16* __restrict__ Kh, const __nv_bfloat16* __restrict__ Kl,
          const __nv_bfloat16* __restrict__ Vh, const __nv_bfloat16* __restrict__ Vl,
          const __nv_bfloat16* __restrict__ Wqh, const __nv_bfloat16* __restrict__ Wql,
          const __nv_bfloat16* __restrict__ Wkh, const __nv_bfloat16* __restrict__ Wkl,
          const __nv_bfloat16* __restrict__ Wvh, const __nv_bfloat16* __restrict__ Wvl,
          const float* __restrict__ bq, const float* __restrict__ bk,
          const float* __restrict__ bv,
          __nv_bfloat16* __restrict__ Qph, __nv_bfloat16* __restrict__ Qpl,
          float* __restrict__ Kp, float* __restrict__ Vp)
{
    extern __shared__ __align__(16) __nv_bfloat16 smem[];
    const int tid = threadIdx.x, lane = tid & 31, wid = tid >> 5;
    const int z = blockIdx.z;

    GemmCore core;
    const float* bias;
    if (z == 0)      { core.Ah = Qh; core.Al = Ql; core.Bh = Wqh; core.Bl = Wql; bias = bq; }
    else if (z == 1) { core.Ah = Kh; core.Al = Kl; core.Bh = Wkh; core.Bl = Wkl; bias = bk; }
    else             { core.Ah = Vh; core.Al = Vl; core.Bh = Wvh; core.Bl = Wvl; bias = bv; }
    core.m0 = blockIdx.y * 128; core.n0 = blockIdx.x * 128; core.K = DM;

    float acc[4][4][4];
    #pragma unroll
    for (int i = 0; i < 4; i++)
        #pragma unroll
        for (int j = 0; j < 4; j++)
            #pragma unroll
            for (int r = 0; r < 4; r++) acc[i][j][r] = 0.f;

    core.run(smem, acc, tid, lane, wid);

    const int m_warp = (wid >> 2) * 64;
    const int n_warp = (wid & 3) * 32;
    const int N = DM;
    float* Cf = (z == 1) ? Kp : Vp;

    #pragma unroll
    for (int tm = 0; tm < 4; tm++) {
        #pragma unroll
        for (int tn = 0; tn < 4; tn++) {
            const int row = core.m0 + m_warp + tm * 16 + (lane >> 2);
            const int col = core.n0 + n_warp + tn * 8 + (lane & 3) * 2;
            const float2 bb = *(const float2*)&bias[col];
            float2 v0 = make_float2(acc[tm][tn][0] + bb.x, acc[tm][tn][1] + bb.y);
            float2 v1 = make_float2(acc[tm][tn][2] + bb.x, acc[tm][tn][3] + bb.y);
            if (z == 0) {
                __nv_bfloat16 h0, l0, h1, l1;
                split1(v0.x, h0, l0); split1(v0.y, h1, l1);
                *(__nv_bfloat162*)&Qph[(long long)row * N + col] = __nv_bfloat162(h0, h1);
                *(__nv_bfloat162*)&Qpl[(long long)row * N + col] = __nv_bfloat162(l0, l1);
                split1(v1.x, h0, l0); split1(v1.y, h1, l1);
                *(__nv_bfloat162*)&Qph[(long long)(row + 8) * N + col] = __nv_bfloat162(h0, h1);
                *(__nv_bfloat162*)&Qpl[(long long)(row + 8) * N + col] = __nv_bfloat162(l0, l1);
            } else {
                *(float2*)&Cf[(long long)row * N + col] = v0;
                *(float2*)&Cf[(long long)(row + 8) * N + col] = v1;
            }
        }
    }
}

// ---------------------------------------------------------------------------
// Merged input splits: grid.z selects {Q, K, V, Wq, Wk, Wv}
// ---------------------------------------------------------------------------
__global__ void __launch_bounds__(256)
split_all_kernel(const float* __restrict__ Q, const float* __restrict__ K,
                 const float* __restrict__ V, const float* __restrict__ Wq,
                 const float* __restrict__ Wk, const float* __restrict__ Wv,
                 __nv_bfloat16* __restrict__ Qh, __nv_bfloat16* __restrict__ Ql,
                 __nv_bfloat16* __restrict__ Kh, __nv_bfloat16* __restrict__ Kl,
                 __nv_bfloat16* __restrict__ Vh, __nv_bfloat16* __restrict__ Vl,
                 __nv_bfloat16* __restrict__ Wqh, __nv_bfloat16* __restrict__ Wql,
                 __nv_bfloat16* __restrict__ Wkh, __nv_bfloat16* __restrict__ Wkl,
                 __nv_bfloat16* __restrict__ Wvh, __nv_bfloat16* __restrict__ Wvl)
{
    const int z = blockIdx.z;
    const long long bigN4 = ((long long)BATCH * NQ * DM) >> 2;   // 2,097,152
    const long long wN4   = ((long long)DM * DM) >> 2;           // 262,144
    const float* src; __nv_bfloat16 *hi, *lo; long long n4;
    switch (z) {
        case 0: src = Q;  hi = Qh;  lo = Ql;  n4 = bigN4; break;
        case 1: src = K;  hi = Kh;  lo = Kl;  n4 = bigN4; break;
        case 2: src = V;  hi = Vh;  lo = Vl;  n4 = bigN4; break;
        case 3: src = Wq; hi = Wqh; lo = Wql; n4 = wN4;   break;
        case 4: src = Wk; hi = Wkh; lo = Wkl; n4 = wN4;   break;
        default: src = Wv; hi = Wvh; lo = Wvl; n4 = wN4;  break;
    }
    const long long i = (long long)blockIdx.x * blockDim.x + threadIdx.x;
    if (i >= n4) return;
    const float4 v = ((const float4*)src)[i];
    __nv_bfloat16 h0, h1, h2, h3, l0, l1, l2, l3;
    split1(v.x, h0, l0); split1(v.y, h1, l1); split1(v.z, h2, l2); split1(v.w, h3, l3);
    ((__nv_bfloat162*)hi)[2*i]   = __nv_bfloat162(h0, h1);
    ((__nv_bfloat162*)hi)[2*i+1] = __nv_bfloat162(h2, h3);
    ((__nv_bfloat162*)lo)[2*i]   = __nv_bfloat162(l0, l1);
    ((__nv_bfloat162*)lo)[2*i+1] = __nv_bfloat162(l2, l3);
}

// Vp [b, 2048, 1024] fp32 -> VpT [b, 1024, 2048] split bf16
__global__ void __launch_bounds__(256) transpose_split_kernel(const float* __restrict__ src,
                                                              __nv_bfloat16* __restrict__ dhi,
                                                              __nv_bfloat16* __restrict__ dlo)
{
    __shared__ float tile[32][33];
    const long long b = blockIdx.z;
    const float* S = src + b * (long long)NK * DM;
    const int x0 = blockIdx.x * 32;
    const int y0 = blockIdx.y * 32;
    #pragma unroll
    for (int j = 0; j < 32; j += 8)
        tile[threadIdx.y + j][threadIdx.x] =
            S[(long long)(y0 + threadIdx.y + j) * DM + x0 + threadIdx.x];
    __syncthreads();
    __nv_bfloat16* Hh = dhi + b * (long long)DM * NK;
    __nv_bfloat16* Hl = dlo + b * (long long)DM * NK;
    #pragma unroll
    for (int j = 0; j < 32; j += 8) {
        const float v = tile[threadIdx.x][threadIdx.y + j];
        const int orow = x0 + threadIdx.y + j;
        const int ocol = y0 + threadIdx.x;
        __nv_bfloat16 h, l;
        split1(v, h, l);
        Hh[(long long)orow * NK + ocol] = h;
        Hl[(long long)orow * NK + ocol] = l;
    }
}

// ---------------------------------------------------------------------------
// Row reductions
// ---------------------------------------------------------------------------
__device__ __forceinline__ float warp_max(float v) {
    #pragma unroll
    for (int o = 16; o; o >>= 1) v = fmaxf(v, __shfl_xor_sync(0xffffffffu, v, o));
    return v;
}
__device__ __forceinline__ float warp_sum(float v) {
    #pragma unroll
    for (int o = 16; o; o >>= 1) v += __shfl_xor_sync(0xffffffffu, v, o);
    return v;
}
__device__ __forceinline__ float block_reduce_max(float v, float* sred, int t) {
    v = warp_max(v);
    if ((t & 31) == 0) sred[t >> 5] = v;
    __syncthreads();
    if (t < 32) {
        float x = (t < 8) ? sred[t] : -INFINITY;
        #pragma unroll
        for (int o = 4; o; o >>= 1) x = fmaxf(x, __shfl_xor_sync(0xffffffffu, x, o));
        if (t == 0) sred[0] = x;
    }
    __syncthreads();
    const float r = sred[0];
    __syncthreads();
    return r;
}
__device__ __forceinline__ float block_reduce_sum(float v, float* sred, int t) {
    v = warp_sum(v);
    if ((t & 31) == 0) sred[t >> 5] = v;
    __syncthreads();
    if (t < 32) {
        float x = (t < 8) ? sred[t] : 0.f;
        #pragma unroll
        for (int o = 4; o; o >>= 1) x += __shfl_xor_sync(0xffffffffu, x, o);
        if (t == 0) sred[0] = x;
    }
    __syncthreads();
    const float r = sred[0];
    __syncthreads();
    return r;
}

// pK = softmax(Kp row) split bf16; negent[row] = sum p*logp. D = 1024
__global__ void __launch_bounds__(256)
softmax_ent_split_rows(const float* __restrict__ X,
                       __nv_bfloat16* __restrict__ Hh, __nv_bfloat16* __restrict__ Hl,
                       float* __restrict__ negent)
{
    const float* row = X + (size_t)blockIdx.x * DM;
    const int t = threadIdx.x;
    __shared__ float sred[8];
    float x[4];
    #pragma unroll
    for (int i = 0; i < 4; i++) x[i] = row[t + 256 * i];
    float m = fmaxf(fmaxf(x[0], x[1]), fmaxf(x[2], x[3]));
    m = block_reduce_max(m, sred, t);
    float s = 0.f;
    #pragma unroll
    for (int i = 0; i < 4; i++) s += expf(x[i] - m);
    s = block_reduce_sum(s, sred, t);
    const float lse = m + logf(s);
    const size_t base = (size_t)blockIdx.x * DM + t;
    float se = 0.f;
    #pragma unroll
    for (int i = 0; i < 4; i++) {
        const float lp = x[i] - lse;
        const float p = expf(lp);
        se += p * lp;
        __nv_bfloat16 h, l;
        split1(p, h, l);
        Hh[base + 256 * i] = h;
        Hl[base + 256 * i] = l;
    }
    se = warp_sum(se);
    if ((t & 31) == 0) sred[t >> 5] = se;
    __syncthreads();
    if (t < 32) {
        float v = (t < 8) ? sred[t] : 0.f;
        #pragma unroll
        for (int o = 4; o; o >>= 1) v += __shfl_xor_sync(0xffffffffu, v, o);
        if (t == 0) negent[blockIdx.x] = v;
    }
}

// attn = softmax(scores row) in place (fp32) + split bf16. D = 2048
__global__ void __launch_bounds__(256)
attn_softmax_split_rows(float* __restrict__ X,
                        __nv_bfloat16* __restrict__ Hh, __nv_bfloat16* __restrict__ Hl)
{
    float* row = X + (size_t)blockIdx.x * NK;
    const int t = threadIdx.x;
    __shared__ float sred[8];
    float x[8];
    #pragma unroll
    for (int i = 0; i < 8; i++) x[i] = row[t + 256 * i];
    float m = -INFINITY;
    #pragma unroll
    for (int i = 0; i < 8; i++) m = fmaxf(m, x[i]);
    m = block_reduce_max(m, sred, t);
    float ex[8];
    float s = 0.f;
    #pragma unroll
    for (int i = 0; i < 8; i++) { ex[i] = expf(x[i] - m); s += ex[i]; }
    s = block_reduce_sum(s, sred, t);
    const float inv = 1.f / s;
    const size_t base = (size_t)blockIdx.x * NK + t;
    #pragma unroll
    for (int i = 0; i < 8; i++) {
        const float p = ex[i] * inv;
        row[t + 256 * i] = p;
        __nv_bfloat16 h, l;
        split1(p, h, l);
        Hh[base + 256 * i] = h;
        Hl[base + 256 * i] = l;
    }
}

// ---------------------------------------------------------------------------
// Launch
// ---------------------------------------------------------------------------
extern "C" void kernel_launch(void* const* d_in, const int* in_sizes, int n_in,
                              void* d_out, int out_size)
{
    const float* Q  = (const float*)d_in[0];
    const float* K  = (const float*)d_in[1];
    const float* V  = (const float*)d_in[2];
    const float* Wq = (const float*)d_in[3];
    const float* bq = (const float*)d_in[4];
    const float* Wk = (const float*)d_in[5];
    const float* bk = (const float*)d_in[6];
    const float* Wv = (const float*)d_in[7];
    const float* bv = (const float*)d_in[8];

    float* out = (float*)d_out;
    const long long outElems  = (long long)BATCH * NQ * DM;
    const long long attnElems = (long long)BATCH * NQ * NK;

    cudaFuncSetAttribute(wm_gemm<0>, cudaFuncAttributeMaxDynamicSharedMemorySize, GEMM_SMEM);
    cudaFuncSetAttribute(wm_gemm<2>, cudaFuncAttributeMaxDynamicSharedMemorySize, GEMM_SMEM);
    cudaFuncSetAttribute(proj_gemm, cudaFuncAttributeMaxDynamicSharedMemorySize, GEMM_SMEM);

    float *Kp, *Vp, *negent, *attn_scratch;
    cudaGetSymbolAddress((void**)&Kp, g_Kp);
    cudaGetSymbolAddress((void**)&Vp, g_Vp);
    cudaGetSymbolAddress((void**)&negent, g_negent);
    cudaGetSymbolAddress((void**)&attn_scratch, g_attn);
    float* attn = ((long long)out_size >= outElems + attnElems) ? (out + outElems) : attn_scratch;

    __nv_bfloat16 *Qh, *Ql, *Kh, *Kl, *Vh, *Vl, *Wqh, *Wql, *Wkh, *Wkl, *Wvh, *Wvl;
    __nv_bfloat16 *Qph, *Qpl, *pKh, *pKl, *VpTh, *VpTl, *Ath, *Atl;
    cudaGetSymbolAddress((void**)&Qh, g_Qh);   cudaGetSymbolAddress((void**)&Ql, g_Ql);
    cudaGetSymbolAddress((void**)&Kh, g_Kh);   cudaGetSymbolAddress((void**)&Kl, g_Kl);
    cudaGetSymbolAddress((void**)&Vh, g_Vh);   cudaGetSymbolAddress((void**)&Vl, g_Vl);
    cudaGetSymbolAddress((void**)&Wqh, g_Wqh); cudaGetSymbolAddress((void**)&Wql, g_Wql);
    cudaGetSymbolAddress((void**)&Wkh, g_Wkh); cudaGetSymbolAddress((void**)&Wkl, g_Wkl);
    cudaGetSymbolAddress((void**)&Wvh, g_Wvh); cudaGetSymbolAddress((void**)&Wvl, g_Wvl);
    cudaGetSymbolAddress((void**)&Qph, g_Qph); cudaGetSymbolAddress((void**)&Qpl, g_Qpl);
    cudaGetSymbolAddress((void**)&pKh, g_pKh); cudaGetSymbolAddress((void**)&pKl, g_pKl);
    cudaGetSymbolAddress((void**)&VpTh, g_VpTh); cudaGetSymbolAddress((void**)&VpTl, g_VpTl);
    cudaGetSymbolAddress((void**)&Ath, g_Ath); cudaGetSymbolAddress((void**)&Atl, g_Atl);

    const int Mrows = BATCH * NQ;  // 8192

    // 1) all input splits in one launch
    {
        const long long bigN4 = ((long long)Mrows * DM) >> 2;
        dim3 grid((unsigned)((bigN4 + 255) / 256), 1, 6);
        split_all_kernel<<<grid, 256>>>(Q, K, V, Wq, Wk, Wv,
                                        Qh, Ql, Kh, Kl, Vh, Vl,
                                        Wqh, Wql, Wkh, Wkl, Wvh, Wvl);
    }

    // 2) merged projections; Q epilogue writes split bf16 directly
    {
        dim3 grid(DM / 128, Mrows / 128, 3);
        proj_gemm<<<grid, 256, GEMM_SMEM>>>(Qh, Ql, Kh, Kl, Vh, Vl,
                                            Wqh, Wql, Wkh, Wkl, Wvh, Wvl,
                                            bq, bk, bv, Qph, Qpl, Kp, Vp);
    }

    // 3) pK split + negent; transpose+split Vp
    softmax_ent_split_rows<<<Mrows, 256>>>(Kp, pKh, pKl, negent);
    {
        dim3 grid(DM / 32, NK / 32, BATCH);
        transpose_split_kernel<<<grid, dim3(32, 8)>>>(Vp, VpTh, VpTl);
    }

    // 4) scores[b,i,j] = Qp_i . pK_j - negent[j]   (lse_i shift drops in softmax)
    {
        dim3 grid(NK / 128, NQ / 128, BATCH);
        wm_gemm<2><<<grid, 256, GEMM_SMEM>>>(
            Qph, Qpl, pKh, pKl, negent, attn, NQ, NK, DM,
            (long long)NQ * DM, (long long)NK * DM, (long long)NQ * NK, (long long)NK);
    }

    // 5) attn = softmax(scores) fp32 + split bf16
    attn_softmax_split_rows<<<BATCH * NQ, 256>>>(attn, Ath, Atl);

    // 6) out = attn @ Vp (via VpT, NT form)
    {
        dim3 grid(DM / 128, NQ / 128, BATCH);
        wm_gemm<0><<<grid, 256, GEMM_SMEM>>>(
            Ath, Atl, VpTh, VpTl, nullptr, out, NQ, DM, NK,
            (long long)NQ * NK, (long long)DM * NK, (long long)NQ * DM, 0);
    }
}